// round 2
// baseline (speedup 1.0000x reference)
#include <cuda_runtime.h>
#include <math.h>

#define BATCH 1024
#define T     127
#define ENC   256
#define DEC   256
#define GATES (4*DEC)

// ---------------- scratch (device globals: no allocation allowed) -----------
__device__ float g_Ue[(size_t)BATCH * T * ENC];     // 133 MB
__device__ float g_h[2][BATCH * DEC];
__device__ float g_c[2][BATCH * DEC];
__device__ float g_Wd[BATCH * ENC];
__device__ float g_ctx[BATCH * ENC];
__device__ float g_yt[BATCH];
__device__ float g_gates[(size_t)BATCH * GATES];    // 4 MB

// ---------------- init ------------------------------------------------------
__global__ void k_zero_state() {
    int i = blockIdx.x * 256 + threadIdx.x;
    g_h[0][i] = 0.f;
    g_c[0][i] = 0.f;
}

// ---------------- generic tiled GEMM: C = [A1|A2] @ W^T (+bias) -------------
// A1: (M, K1) row-major, A2: (M, K-K1) row-major (concat along K; pass K1==K
// to use A1 only). W: (N, K) row-major. C: (M, N). Dims divisible by tiles.
#define BM 64
#define BN 64
#define BKK 16

__global__ __launch_bounds__(256) void k_gemm_abT(
    const float* __restrict__ A1, const float* __restrict__ A2, int K1,
    const float* __restrict__ W, const float* __restrict__ bias,
    float* __restrict__ C, int M, int N, int K)
{
    __shared__ float sA[BKK][BM];
    __shared__ float sB[BKK][BN];
    int tid  = threadIdx.x;
    int row0 = blockIdx.y * BM;
    int col0 = blockIdx.x * BN;
    int tx = tid & 15, ty = tid >> 4;
    int Kb = K - K1;
    float acc[4][4] = {};

    for (int k0 = 0; k0 < K; k0 += BKK) {
        #pragma unroll
        for (int i = 0; i < 4; i++) {
            int lin = tid + i * 256;
            int k = lin & 15, m = lin >> 4;
            int kg = k0 + k;
            float v;
            if (kg < K1) v = A1[(size_t)(row0 + m) * K1 + kg];
            else         v = A2[(size_t)(row0 + m) * Kb + (kg - K1)];
            sA[k][m] = v;
        }
        #pragma unroll
        for (int i = 0; i < 4; i++) {
            int lin = tid + i * 256;
            int k = lin & 15, n = lin >> 4;
            sB[k][n] = W[(size_t)(col0 + n) * K + (k0 + k)];
        }
        __syncthreads();
        #pragma unroll
        for (int k = 0; k < BKK; k++) {
            float a[4], bv[4];
            #pragma unroll
            for (int i = 0; i < 4; i++) a[i] = sA[k][ty * 4 + i];
            #pragma unroll
            for (int j = 0; j < 4; j++) bv[j] = sB[k][tx * 4 + j];
            #pragma unroll
            for (int i = 0; i < 4; i++)
                #pragma unroll
                for (int j = 0; j < 4; j++)
                    acc[i][j] = fmaf(a[i], bv[j], acc[i][j]);
        }
        __syncthreads();
    }
    #pragma unroll
    for (int i = 0; i < 4; i++) {
        int m = row0 + ty * 4 + i;
        #pragma unroll
        for (int j = 0; j < 4; j++) {
            int n = col0 + tx * 4 + j;
            float v = acc[i][j];
            if (bias) v += bias[n];
            C[(size_t)m * N + n] = v;
        }
    }
}

// ---------------- fused attention step: scores->softmax->context->y_tilde ---
// one block per batch element, 256 threads (8 warps)
__global__ __launch_bounds__(256) void k_attn(
    const float* __restrict__ X,       // input_encoded (B, T, ENC)
    const float* __restrict__ Wvd,     // (ENC)
    const float* __restrict__ bvd,     // (1)
    const float* __restrict__ Ww,      // (1+ENC) [ctx part 0..ENC-1, y at ENC]
    const float* __restrict__ bw,      // (1)
    const float* __restrict__ yhist,   // (B, T)
    int step)
{
    int b = blockIdx.x;
    int tid = threadIdx.x, lane = tid & 31, warp = tid >> 5;
    __shared__ float s_wd[ENC];
    __shared__ float s_wv[ENC];
    __shared__ float s_sc[128];
    __shared__ float s_part[8];
    __shared__ float s_bcast;

    s_wd[tid] = g_Wd[b * ENC + tid];
    s_wv[tid] = Wvd[tid];
    __syncthreads();

    const float* ue = g_Ue + (size_t)b * T * ENC;
    float bv = bvd[0];

    // scores[t] = sum_e tanh(Wd[e] + Ue[t,e]) * Wvd[e] + bv
    for (int t = warp; t < T; t += 8) {
        const float* row = ue + t * ENC;
        float acc = 0.f;
        #pragma unroll
        for (int i = 0; i < ENC / 32; i++) {
            int e = i * 32 + lane;
            acc = fmaf(tanhf(s_wd[e] + row[e]), s_wv[e], acc);
        }
        #pragma unroll
        for (int o = 16; o; o >>= 1) acc += __shfl_xor_sync(0xffffffffu, acc, o);
        if (lane == 0) s_sc[t] = acc + bv;
    }
    __syncthreads();

    // softmax over T=127
    float v = (tid < T) ? s_sc[tid] : -3.4e38f;
    float m = v;
    #pragma unroll
    for (int o = 16; o; o >>= 1) m = fmaxf(m, __shfl_xor_sync(0xffffffffu, m, o));
    if (lane == 0) s_part[warp] = m;
    __syncthreads();
    if (tid == 0) {
        float mm = s_part[0];
        #pragma unroll
        for (int i = 1; i < 8; i++) mm = fmaxf(mm, s_part[i]);
        s_bcast = mm;
    }
    __syncthreads();
    float mx = s_bcast;
    float ev = (tid < T) ? expf(v - mx) : 0.f;
    if (tid < T) s_sc[tid] = ev;
    float sum = ev;
    #pragma unroll
    for (int o = 16; o; o >>= 1) sum += __shfl_xor_sync(0xffffffffu, sum, o);
    if (lane == 0) s_part[warp] = sum;
    __syncthreads();
    if (tid == 0) {
        float ss = 0.f;
        #pragma unroll
        for (int i = 0; i < 8; i++) ss += s_part[i];
        s_bcast = ss;
    }
    __syncthreads();
    float inv = 1.f / s_bcast;

    // context[e] = sum_t beta[t] * X[b,t,e]
    const float* xb = X + (size_t)b * T * ENC;
    float acc = 0.f;
    #pragma unroll 4
    for (int t = 0; t < T; t++)
        acc = fmaf(s_sc[t], xb[t * ENC + tid], acc);
    acc *= inv;
    g_ctx[b * ENC + tid] = acc;

    // y_tilde = ctx . Ww[0:ENC] + y_t * Ww[ENC] + bw
    float yv = acc * Ww[tid];
    #pragma unroll
    for (int o = 16; o; o >>= 1) yv += __shfl_xor_sync(0xffffffffu, yv, o);
    if (lane == 0) s_part[warp] = yv;
    __syncthreads();
    if (tid == 0) {
        float ss = 0.f;
        #pragma unroll
        for (int i = 0; i < 8; i++) ss += s_part[i];
        g_yt[b] = ss + yhist[b * T + step] * Ww[ENC] + bw[0];
    }
}

// ---------------- LSTM cell elementwise (gates GEMM result in g_gates) ------
__global__ __launch_bounds__(256) void k_cell(
    const float* __restrict__ Wih, const float* __restrict__ bih,
    const float* __restrict__ bhh, int cur)
{
    int idx = blockIdx.x * 256 + threadIdx.x;     // b*DEC + d
    int b = idx >> 8, d = idx & 255;
    float yt = g_yt[b];
    const float* gb = g_gates + (size_t)b * GATES;
    float gi = gb[d]           + yt * Wih[d]           + bih[d]           + bhh[d];
    float gf = gb[DEC + d]     + yt * Wih[DEC + d]     + bih[DEC + d]     + bhh[DEC + d];
    float gg = gb[2 * DEC + d] + yt * Wih[2 * DEC + d] + bih[2 * DEC + d] + bhh[2 * DEC + d];
    float go = gb[3 * DEC + d] + yt * Wih[3 * DEC + d] + bih[3 * DEC + d] + bhh[3 * DEC + d];
    float ig = 1.f / (1.f + expf(-gi));
    float fg = 1.f / (1.f + expf(-gf));
    float gt = tanhf(gg);
    float og = 1.f / (1.f + expf(-go));
    float cn = fg * g_c[cur][idx] + ig * gt;
    g_c[cur ^ 1][idx] = cn;
    g_h[cur ^ 1][idx] = og * tanhf(cn);
}

// ---------------- final projection ------------------------------------------
__global__ __launch_bounds__(256) void k_final(
    const float* __restrict__ Wfc, const float* __restrict__ bfc,
    float* __restrict__ out, int fin)
{
    int b = blockIdx.x, tid = threadIdx.x, lane = tid & 31, warp = tid >> 5;
    __shared__ float s_part[8];
    float v = g_h[fin][b * DEC + tid] * Wfc[tid]
            + g_ctx[b * ENC + tid] * Wfc[DEC + tid];
    #pragma unroll
    for (int o = 16; o; o >>= 1) v += __shfl_xor_sync(0xffffffffu, v, o);
    if (lane == 0) s_part[warp] = v;
    __syncthreads();
    if (tid == 0) {
        float ss = 0.f;
        #pragma unroll
        for (int i = 0; i < 8; i++) ss += s_part[i];
        out[b] = ss + bfc[0];
    }
}

// ---------------- host ------------------------------------------------------
extern "C" void kernel_launch(void* const* d_in, const int* in_sizes, int n_in,
                              void* d_out, int out_size)
{
    const float* X     = (const float*)d_in[0];   // (B, T, ENC)
    const float* yhist = (const float*)d_in[1];   // (B, T)
    const float* W_vd  = (const float*)d_in[2];
    const float* b_vd  = (const float*)d_in[3];
    const float* W_dhs = (const float*)d_in[4];   // (ENC, 2*DEC)
    const float* b_dhs = (const float*)d_in[5];
    const float* W_Ud  = (const float*)d_in[6];   // (ENC, ENC)
    const float* b_Ud  = (const float*)d_in[7];
    const float* W_w   = (const float*)d_in[8];   // (1, 1+ENC)
    const float* b_w   = (const float*)d_in[9];
    const float* W_ih  = (const float*)d_in[10];  // (4*DEC, 1)
    const float* W_hh  = (const float*)d_in[11];  // (4*DEC, DEC)
    const float* b_ih  = (const float*)d_in[12];
    const float* b_hh  = (const float*)d_in[13];
    const float* W_fc  = (const float*)d_in[14];  // (1, DEC+ENC)
    const float* b_fc  = (const float*)d_in[15];
    float* out = (float*)d_out;

    void *p_Ue, *p_h, *p_c, *p_Wd, *p_gates;
    cudaGetSymbolAddress(&p_Ue, g_Ue);
    cudaGetSymbolAddress(&p_h, g_h);
    cudaGetSymbolAddress(&p_c, g_c);
    cudaGetSymbolAddress(&p_Wd, g_Wd);
    cudaGetSymbolAddress(&p_gates, g_gates);
    float* Ue = (float*)p_Ue;
    float* hb = (float*)p_h;      // g_h[0] then g_h[1]
    float* cb = (float*)p_c;
    float* Wd = (float*)p_Wd;
    float* gates = (float*)p_gates;

    // init state
    k_zero_state<<<(BATCH * DEC) / 256, 256>>>();

    // Ue = X @ W_Ud^T + b_Ud   (M = B*T, N = ENC, K = ENC)
    {
        dim3 grid(ENC / BN, (BATCH * T) / BM);
        k_gemm_abT<<<grid, 256>>>(X, X, ENC, W_Ud, b_Ud, Ue, BATCH * T, ENC, ENC);
    }

    for (int s = 0; s < T; s++) {
        int cur = s & 1;
        float* h_cur = hb + (size_t)cur * BATCH * DEC;
        float* c_cur = cb + (size_t)cur * BATCH * DEC;

        // Wd = [h|c] @ W_dhs^T + b_dhs   (M=B, N=ENC, K=2*DEC)
        {
            dim3 grid(ENC / BN, BATCH / BM);
            k_gemm_abT<<<grid, 256>>>(h_cur, c_cur, DEC, W_dhs, b_dhs,
                                      Wd, BATCH, ENC, 2 * DEC);
        }
        // attention + softmax + context + y_tilde
        k_attn<<<BATCH, 256>>>(X, W_vd, b_vd, W_w, b_w, yhist, s);

        // gates = h @ W_hh^T   (M=B, N=4*DEC, K=DEC)
        {
            dim3 grid(GATES / BN, BATCH / BM);
            k_gemm_abT<<<grid, 256>>>(h_cur, h_cur, DEC, W_hh, (const float*)0,
                                      gates, BATCH, GATES, DEC);
        }
        // LSTM cell update -> buffers [cur^1]
        k_cell<<<(BATCH * DEC) / 256, 256>>>(W_ih, b_ih, b_hh, cur);
    }

    // y_pred = [h|ctx] @ W_fc^T + b_fc
    k_final<<<BATCH, 256>>>(W_fc, b_fc, out, T & 1);
}

// round 3
// speedup vs baseline: 1.8897x; 1.8897x over previous
#include <cuda_runtime.h>
#include <cuda_fp16.h>
#include <math.h>

#define BATCH 1024
#define T     127
#define ENC   256
#define DEC   256

// ---------------- scratch (device globals) ----------------------------------
__device__ __half g_Ueh[(size_t)BATCH * T * ENC];   // 66.6 MB (half)
__device__ __half g_Xh[(size_t)BATCH * T * ENC];    // 66.6 MB (half)
__device__ float  g_h[2][BATCH * DEC];
__device__ float  g_c[2][BATCH * DEC];
__device__ float  g_Wd[BATCH * ENC];
__device__ float  g_ctx[BATCH * ENC];
__device__ float  g_yt[BATCH];

__device__ __forceinline__ float tanh_fast(float x) {
    float y; asm("tanh.approx.f32 %0, %1;" : "=f"(y) : "f"(x)); return y;
}

// ---------------- init ------------------------------------------------------
__global__ void k_zero_state() {
    int i = blockIdx.x * 256 + threadIdx.x;
    g_h[0][i] = 0.f;
    g_c[0][i] = 0.f;
}

// ---------------- X fp32 -> fp16 --------------------------------------------
__global__ __launch_bounds__(256) void k_convert_x(const float* __restrict__ X) {
    size_t i = ((size_t)blockIdx.x * 256 + threadIdx.x) * 4;
    float4 v = *(const float4*)(X + i);
    __half2 h0 = __floats2half2_rn(v.x, v.y);
    __half2 h1 = __floats2half2_rn(v.z, v.w);
    *(__half2*)(g_Xh + i)     = h0;
    *(__half2*)(g_Xh + i + 2) = h1;
}

// ---------------- Ue GEMM: Ue = X @ W_Ud^T + b, output half ------------------
// M = B*T (130048), N = 256, K = 256. 128x64 tile, BK=16, 8x4 microtile.
__global__ __launch_bounds__(256) void k_gemm_ue(
    const float* __restrict__ X, const float* __restrict__ W,
    const float* __restrict__ bias)
{
    __shared__ float sA[16][128];
    __shared__ float sB[16][64];
    int tid = threadIdx.x;
    int m0 = blockIdx.y * 128;
    int n0 = blockIdx.x * 64;
    int tx = tid & 15, ty = tid >> 4;
    float acc[8][4] = {};

    for (int k0 = 0; k0 < 256; k0 += 16) {
        // load A tile: 128 rows x 16 k, float4 (2 per thread)
        #pragma unroll
        for (int i = 0; i < 2; i++) {
            int lin = tid + i * 256;
            int r = lin >> 2, f4 = lin & 3;
            float4 v = *(const float4*)(X + (size_t)(m0 + r) * 256 + k0 + f4 * 4);
            sA[f4 * 4 + 0][r] = v.x; sA[f4 * 4 + 1][r] = v.y;
            sA[f4 * 4 + 2][r] = v.z; sA[f4 * 4 + 3][r] = v.w;
        }
        // load B tile: 64 rows x 16 k (1 float4 per thread)
        {
            int r = tid >> 2, f4 = tid & 3;
            float4 v = *(const float4*)(W + (size_t)(n0 + r) * 256 + k0 + f4 * 4);
            sB[f4 * 4 + 0][r] = v.x; sB[f4 * 4 + 1][r] = v.y;
            sB[f4 * 4 + 2][r] = v.z; sB[f4 * 4 + 3][r] = v.w;
        }
        __syncthreads();
        #pragma unroll
        for (int k = 0; k < 16; k++) {
            float a[8];
            #pragma unroll
            for (int i = 0; i < 8; i++) a[i] = sA[k][ty * 8 + i];
            float4 bv = *(const float4*)&sB[k][tx * 4];
            #pragma unroll
            for (int i = 0; i < 8; i++) {
                acc[i][0] = fmaf(a[i], bv.x, acc[i][0]);
                acc[i][1] = fmaf(a[i], bv.y, acc[i][1]);
                acc[i][2] = fmaf(a[i], bv.z, acc[i][2]);
                acc[i][3] = fmaf(a[i], bv.w, acc[i][3]);
            }
        }
        __syncthreads();
    }
    float b0 = bias[n0 + tx * 4], b1 = bias[n0 + tx * 4 + 1];
    float b2 = bias[n0 + tx * 4 + 2], b3 = bias[n0 + tx * 4 + 3];
    #pragma unroll
    for (int i = 0; i < 8; i++) {
        size_t m = m0 + ty * 8 + i;
        __half2* dst = (__half2*)(g_Ueh + m * 256 + n0 + tx * 4);
        dst[0] = __floats2half2_rn(acc[i][0] + b0, acc[i][1] + b1);
        dst[1] = __floats2half2_rn(acc[i][2] + b2, acc[i][3] + b3);
    }
}

// ---------------- Wd GEMM: Wd = [h|c] @ W_dhs^T + b --------------------------
// M=1024, N=256, K=512. 32x64 tile, BK=16, 2x4 microtile. grid (4,32)=128 blocks
__global__ __launch_bounds__(256) void k_wd(
    const float* __restrict__ Ah, const float* __restrict__ Ac,
    const float* __restrict__ W, const float* __restrict__ bias)
{
    __shared__ float sA[16][32];
    __shared__ float sB[16][64];
    int tid = threadIdx.x;
    int m0 = blockIdx.y * 32;
    int n0 = blockIdx.x * 64;
    int tx = tid & 15, ty = tid >> 4;
    float acc[2][4] = {};

    for (int k0 = 0; k0 < 512; k0 += 16) {
        if (tid < 128) {
            int r = tid >> 2, f4 = tid & 3;
            int kg = k0 + f4 * 4;
            const float* base = (kg < 256) ? (Ah + (size_t)(m0 + r) * 256 + kg)
                                           : (Ac + (size_t)(m0 + r) * 256 + (kg - 256));
            float4 v = *(const float4*)base;
            sA[f4 * 4 + 0][r] = v.x; sA[f4 * 4 + 1][r] = v.y;
            sA[f4 * 4 + 2][r] = v.z; sA[f4 * 4 + 3][r] = v.w;
        }
        {
            int r = tid >> 2, f4 = tid & 3;
            float4 v = *(const float4*)(W + (size_t)(n0 + r) * 512 + k0 + f4 * 4);
            sB[f4 * 4 + 0][r] = v.x; sB[f4 * 4 + 1][r] = v.y;
            sB[f4 * 4 + 2][r] = v.z; sB[f4 * 4 + 3][r] = v.w;
        }
        __syncthreads();
        #pragma unroll
        for (int k = 0; k < 16; k++) {
            float2 a = *(const float2*)&sA[k][ty * 2];
            float4 bv = *(const float4*)&sB[k][tx * 4];
            acc[0][0] = fmaf(a.x, bv.x, acc[0][0]); acc[0][1] = fmaf(a.x, bv.y, acc[0][1]);
            acc[0][2] = fmaf(a.x, bv.z, acc[0][2]); acc[0][3] = fmaf(a.x, bv.w, acc[0][3]);
            acc[1][0] = fmaf(a.y, bv.x, acc[1][0]); acc[1][1] = fmaf(a.y, bv.y, acc[1][1]);
            acc[1][2] = fmaf(a.y, bv.z, acc[1][2]); acc[1][3] = fmaf(a.y, bv.w, acc[1][3]);
        }
        __syncthreads();
    }
    #pragma unroll
    for (int i = 0; i < 2; i++) {
        int m = m0 + ty * 2 + i;
        #pragma unroll
        for (int j = 0; j < 4; j++) {
            int n = n0 + tx * 4 + j;
            g_Wd[m * 256 + n] = acc[i][j] + bias[n];
        }
    }
}

// ---------------- fused attention step ---------------------------------------
__global__ __launch_bounds__(256) void k_attn(
    const float* __restrict__ Wvd, const float* __restrict__ bvd,
    const float* __restrict__ Ww,  const float* __restrict__ bw,
    const float* __restrict__ yhist, int step)
{
    int b = blockIdx.x;
    int tid = threadIdx.x, lane = tid & 31, warp = tid >> 5;
    __shared__ float s_wd[256];
    __shared__ float s_wv[256];
    __shared__ float s_sc[128];
    __shared__ float s_part[8];
    __shared__ float s_bcast;
    __shared__ float s_cx[128], s_cy[128];

    s_wd[tid] = g_Wd[b * 256 + tid];
    s_wv[tid] = Wvd[tid];
    __syncthreads();

    const __half* ue = g_Ueh + (size_t)b * T * ENC;
    float bv = bvd[0];

    // scores[t] = sum_e tanh(Wd[e] + Ue[t,e]) * Wvd[e] + bv
    for (int t = warp; t < T; t += 8) {
        float4 raw = *(const float4*)(ue + t * 256 + lane * 8);
        const __half2* hp = (const __half2*)&raw;
        int e0 = lane * 8;
        float acc = 0.f;
        #pragma unroll
        for (int j = 0; j < 4; j++) {
            float2 f = __half22float2(hp[j]);
            acc = fmaf(tanh_fast(s_wd[e0 + 2 * j] + f.x),     s_wv[e0 + 2 * j],     acc);
            acc = fmaf(tanh_fast(s_wd[e0 + 2 * j + 1] + f.y), s_wv[e0 + 2 * j + 1], acc);
        }
        #pragma unroll
        for (int o = 16; o; o >>= 1) acc += __shfl_xor_sync(0xffffffffu, acc, o);
        if (lane == 0) s_sc[t] = acc + bv;
    }
    __syncthreads();

    // softmax over T=127
    float v = (tid < T) ? s_sc[tid] : -3.4e38f;
    float m = v;
    #pragma unroll
    for (int o = 16; o; o >>= 1) m = fmaxf(m, __shfl_xor_sync(0xffffffffu, m, o));
    if (lane == 0) s_part[warp] = m;
    __syncthreads();
    if (tid == 0) {
        float mm = s_part[0];
        #pragma unroll
        for (int i = 1; i < 8; i++) mm = fmaxf(mm, s_part[i]);
        s_bcast = mm;
    }
    __syncthreads();
    float mx = s_bcast;
    float ev = (tid < T) ? __expf(v - mx) : 0.f;
    if (tid < T) s_sc[tid] = ev;
    float sum = ev;
    #pragma unroll
    for (int o = 16; o; o >>= 1) sum += __shfl_xor_sync(0xffffffffu, sum, o);
    if (lane == 0) s_part[warp] = sum;
    __syncthreads();
    if (tid == 0) {
        float ss = 0.f;
        #pragma unroll
        for (int i = 0; i < 8; i++) ss += s_part[i];
        s_bcast = ss;
    }
    __syncthreads();
    float inv = 1.f / s_bcast;

    // context: threads 0-127 do even t, 128-255 odd t, half2 columns
    int half_id = tid >> 7;
    int p = tid & 127;
    const __half2* xb = (const __half2*)(g_Xh + (size_t)b * T * ENC);
    float cx = 0.f, cy = 0.f;
    #pragma unroll 4
    for (int t = half_id; t < T; t += 2) {
        float beta = s_sc[t];
        float2 f = __half22float2(xb[t * 128 + p]);
        cx = fmaf(beta, f.x, cx);
        cy = fmaf(beta, f.y, cy);
    }
    if (half_id == 1) { s_cx[p] = cx; s_cy[p] = cy; }
    __syncthreads();
    float yv = 0.f;
    if (half_id == 0) {
        float fx = (cx + s_cx[p]) * inv;
        float fy = (cy + s_cy[p]) * inv;
        g_ctx[b * 256 + 2 * p]     = fx;
        g_ctx[b * 256 + 2 * p + 1] = fy;
        yv = fx * Ww[2 * p] + fy * Ww[2 * p + 1];
    }
    #pragma unroll
    for (int o = 16; o; o >>= 1) yv += __shfl_xor_sync(0xffffffffu, yv, o);
    if (lane == 0 && warp < 4) s_part[warp] = yv;
    __syncthreads();
    if (tid == 0) {
        float ss = s_part[0] + s_part[1] + s_part[2] + s_part[3];
        g_yt[b] = ss + yhist[b * T + step] * Ww[256] + bw[0];
    }
}

// ---------------- fused gates GEMM + LSTM cell -------------------------------
// block covers 64 batch rows x 32 d-cols x 4 gates. grid (8, 16) = 128 blocks.
__global__ __launch_bounds__(256) void k_gates_cell(
    const float* __restrict__ Whh, const float* __restrict__ Wih,
    const float* __restrict__ bih, const float* __restrict__ bhh, int cur)
{
    __shared__ float sH[16][64];
    __shared__ float sW[16][128];
    int tid = threadIdx.x;
    int d0 = blockIdx.x * 32;
    int m0 = blockIdx.y * 64;
    int tx = tid & 15, ty = tid >> 4;
    const float* h_cur = g_h[cur];
    float acc[4][4][2] = {};   // [m][gate][d]

    for (int k0 = 0; k0 < 256; k0 += 16) {
        {
            int r = tid >> 2, f4 = tid & 3;
            float4 v = *(const float4*)(h_cur + (size_t)(m0 + r) * 256 + k0 + f4 * 4);
            sH[f4 * 4 + 0][r] = v.x; sH[f4 * 4 + 1][r] = v.y;
            sH[f4 * 4 + 2][r] = v.z; sH[f4 * 4 + 3][r] = v.w;
        }
        #pragma unroll
        for (int i = 0; i < 2; i++) {
            int lin = tid + i * 256;
            int r = lin >> 2, f4 = lin & 3;   // r in 0..127
            int g = r >> 5, dl = r & 31;
            float4 v = *(const float4*)(Whh + (size_t)(g * 256 + d0 + dl) * 256 + k0 + f4 * 4);
            sW[f4 * 4 + 0][r] = v.x; sW[f4 * 4 + 1][r] = v.y;
            sW[f4 * 4 + 2][r] = v.z; sW[f4 * 4 + 3][r] = v.w;
        }
        __syncthreads();
        #pragma unroll
        for (int k = 0; k < 16; k++) {
            float4 a = *(const float4*)&sH[k][ty * 4];
            float am[4] = {a.x, a.y, a.z, a.w};
            #pragma unroll
            for (int g = 0; g < 4; g++) {
                float2 w = *(const float2*)&sW[k][g * 32 + tx * 2];
                #pragma unroll
                for (int i = 0; i < 4; i++) {
                    acc[i][g][0] = fmaf(am[i], w.x, acc[i][g][0]);
                    acc[i][g][1] = fmaf(am[i], w.y, acc[i][g][1]);
                }
            }
        }
        __syncthreads();
    }

    int nxt = cur ^ 1;
    #pragma unroll
    for (int i = 0; i < 4; i++) {
        int mrow = m0 + ty * 4 + i;
        float yt = g_yt[mrow];
        #pragma unroll
        for (int j = 0; j < 2; j++) {
            int d = d0 + tx * 2 + j;
            float gi = acc[i][0][j] + yt * Wih[d]       + bih[d]       + bhh[d];
            float gf = acc[i][1][j] + yt * Wih[256 + d] + bih[256 + d] + bhh[256 + d];
            float gg = acc[i][2][j] + yt * Wih[512 + d] + bih[512 + d] + bhh[512 + d];
            float go = acc[i][3][j] + yt * Wih[768 + d] + bih[768 + d] + bhh[768 + d];
            float ig = 1.f / (1.f + expf(-gi));
            float fg = 1.f / (1.f + expf(-gf));
            float gt = tanhf(gg);
            float og = 1.f / (1.f + expf(-go));
            int idx = mrow * 256 + d;
            float cn = fg * g_c[cur][idx] + ig * gt;
            g_c[nxt][idx] = cn;
            g_h[nxt][idx] = og * tanhf(cn);
        }
    }
}

// ---------------- final projection -------------------------------------------
__global__ __launch_bounds__(256) void k_final(
    const float* __restrict__ Wfc, const float* __restrict__ bfc,
    float* __restrict__ out, int fin)
{
    int b = blockIdx.x, tid = threadIdx.x, lane = tid & 31, warp = tid >> 5;
    __shared__ float s_part[8];
    float v = g_h[fin][b * 256 + tid] * Wfc[tid]
            + g_ctx[b * 256 + tid] * Wfc[256 + tid];
    #pragma unroll
    for (int o = 16; o; o >>= 1) v += __shfl_xor_sync(0xffffffffu, v, o);
    if (lane == 0) s_part[warp] = v;
    __syncthreads();
    if (tid == 0) {
        float ss = 0.f;
        #pragma unroll
        for (int i = 0; i < 8; i++) ss += s_part[i];
        out[b] = ss + bfc[0];
    }
}

// ---------------- host -------------------------------------------------------
extern "C" void kernel_launch(void* const* d_in, const int* in_sizes, int n_in,
                              void* d_out, int out_size)
{
    const float* X     = (const float*)d_in[0];
    const float* yhist = (const float*)d_in[1];
    const float* W_vd  = (const float*)d_in[2];
    const float* b_vd  = (const float*)d_in[3];
    const float* W_dhs = (const float*)d_in[4];
    const float* b_dhs = (const float*)d_in[5];
    const float* W_Ud  = (const float*)d_in[6];
    const float* b_Ud  = (const float*)d_in[7];
    const float* W_w   = (const float*)d_in[8];
    const float* b_w   = (const float*)d_in[9];
    const float* W_ih  = (const float*)d_in[10];
    const float* W_hh  = (const float*)d_in[11];
    const float* b_ih  = (const float*)d_in[12];
    const float* b_hh  = (const float*)d_in[13];
    const float* W_fc  = (const float*)d_in[14];
    const float* b_fc  = (const float*)d_in[15];
    float* out = (float*)d_out;

    void *p_h, *p_c;
    cudaGetSymbolAddress(&p_h, g_h);
    cudaGetSymbolAddress(&p_c, g_c);
    float* hb = (float*)p_h;
    float* cb = (float*)p_c;

    k_zero_state<<<(BATCH * DEC) / 256, 256>>>();
    k_convert_x<<<(BATCH * T * ENC) / 4 / 256, 256>>>(X);
    {
        dim3 grid(ENC / 64, (BATCH * T) / 128);
        k_gemm_ue<<<grid, 256>>>(X, W_Ud, b_Ud);
    }

    for (int s = 0; s < T; s++) {
        int cur = s & 1;
        float* h_cur = hb + (size_t)cur * BATCH * DEC;
        float* c_cur = cb + (size_t)cur * BATCH * DEC;
        {
            dim3 grid(ENC / 64, BATCH / 32);
            k_wd<<<grid, 256>>>(h_cur, c_cur, W_dhs, b_dhs);
        }
        k_attn<<<BATCH, 256>>>(W_vd, b_vd, W_w, b_w, yhist, s);
        {
            dim3 grid(DEC / 32, BATCH / 64);
            k_gates_cell<<<grid, 256>>>(W_hh, W_ih, b_ih, b_hh, cur);
        }
    }

    k_final<<<BATCH, 256>>>(W_fc, b_fc, out, T & 1);
}

// round 5
// speedup vs baseline: 1.9800x; 1.0477x over previous
#include <cuda_runtime.h>
#include <cuda_fp16.h>
#include <math.h>

#define BATCH 1024
#define T     127
#define ENC   256
#define DEC   256

// ---------------- scratch (device globals) ----------------------------------
__device__ __half g_Ueh[(size_t)BATCH * T * ENC];   // 66.6 MB
__device__ __half g_Xh[(size_t)BATCH * T * ENC];    // 66.6 MB
__device__ float  g_h[2][BATCH * DEC];
__device__ float  g_c[2][BATCH * DEC];
__device__ float  g_WdP[2][BATCH * ENC];            // split-K partials
__device__ float  g_gates[(size_t)BATCH * 4 * DEC];
__device__ float  g_ctx[BATCH * ENC];
__device__ float  g_yt[BATCH];

__device__ __forceinline__ float tanh_fast(float x) {
    float y; asm("tanh.approx.f32 %0, %1;" : "=f"(y) : "f"(x)); return y;
}

// ---------------- init ------------------------------------------------------
__global__ void k_zero_state() {
    int i = blockIdx.x * 256 + threadIdx.x;
    g_h[0][i] = 0.f;
    g_c[0][i] = 0.f;
}

// ---------------- Ue GEMM (+ fused X->half convert on n-tile 0) --------------
// M = B*T, N = 256, K = 256. 128x64 tile, BK=16, 8x4 microtile.
__global__ __launch_bounds__(256) void k_gemm_ue(
    const float* __restrict__ X, const float* __restrict__ W,
    const float* __restrict__ bias)
{
    __shared__ float sA[16][132];
    __shared__ float sB[16][68];
    int tid = threadIdx.x;
    int m0 = blockIdx.y * 128;
    int n0 = blockIdx.x * 64;
    int tx = tid & 15, ty = tid >> 4;
    bool cvt = (blockIdx.x == 0);
    float acc[8][4] = {};

    for (int k0 = 0; k0 < 256; k0 += 16) {
        #pragma unroll
        for (int i = 0; i < 2; i++) {
            int lin = tid + i * 256;
            int r = lin >> 2, f4 = lin & 3;
            size_t off = (size_t)(m0 + r) * 256 + k0 + f4 * 4;
            float4 v = *(const float4*)(X + off);
            sA[f4 * 4 + 0][r] = v.x; sA[f4 * 4 + 1][r] = v.y;
            sA[f4 * 4 + 2][r] = v.z; sA[f4 * 4 + 3][r] = v.w;
            if (cvt) {
                __half2* dst = (__half2*)(g_Xh + off);
                dst[0] = __floats2half2_rn(v.x, v.y);
                dst[1] = __floats2half2_rn(v.z, v.w);
            }
        }
        {
            int r = tid >> 2, f4 = tid & 3;
            float4 v = *(const float4*)(W + (size_t)(n0 + r) * 256 + k0 + f4 * 4);
            sB[f4 * 4 + 0][r] = v.x; sB[f4 * 4 + 1][r] = v.y;
            sB[f4 * 4 + 2][r] = v.z; sB[f4 * 4 + 3][r] = v.w;
        }
        __syncthreads();
        #pragma unroll
        for (int k = 0; k < 16; k++) {
            float a[8];
            #pragma unroll
            for (int i = 0; i < 8; i++) a[i] = sA[k][ty * 8 + i];
            float4 bv = *(const float4*)&sB[k][tx * 4];
            #pragma unroll
            for (int i = 0; i < 8; i++) {
                acc[i][0] = fmaf(a[i], bv.x, acc[i][0]);
                acc[i][1] = fmaf(a[i], bv.y, acc[i][1]);
                acc[i][2] = fmaf(a[i], bv.z, acc[i][2]);
                acc[i][3] = fmaf(a[i], bv.w, acc[i][3]);
            }
        }
        __syncthreads();
    }
    float b0 = bias[n0 + tx * 4], b1 = bias[n0 + tx * 4 + 1];
    float b2 = bias[n0 + tx * 4 + 2], b3 = bias[n0 + tx * 4 + 3];
    #pragma unroll
    for (int i = 0; i < 8; i++) {
        size_t m = m0 + ty * 8 + i;
        __half2* dst = (__half2*)(g_Ueh + m * 256 + n0 + tx * 4);
        dst[0] = __floats2half2_rn(acc[i][0] + b0, acc[i][1] + b1);
        dst[1] = __floats2half2_rn(acc[i][2] + b2, acc[i][3] + b3);
    }
}

// ---------------- Wd split-K GEMM, double-buffered ---------------------------
// grid (4, 32, 2): 32x64 tile, z picks h (K 0:256) or c (K 256:512).
__global__ __launch_bounds__(256) void k_wd(const float* __restrict__ W, int cur)
{
    int z = blockIdx.z;
    const float* A = z ? g_c[cur] : g_h[cur];
    const float* Wb = W + z * 256;                 // W_dhs rows have stride 512
    __shared__ float sA[2][16][36];
    __shared__ float sB[2][16][68];
    int tid = threadIdx.x;
    int m0 = blockIdx.y * 32, n0 = blockIdx.x * 64;
    int tx = tid & 15, ty = tid >> 4;
    int r = tid >> 2, f4 = tid & 3;
    float acc[2][4] = {};
    float4 ra, rb;

    if (tid < 128) ra = *(const float4*)(A + (size_t)(m0 + r) * 256 + f4 * 4);
    rb = *(const float4*)(Wb + (size_t)(n0 + r) * 512 + f4 * 4);
    if (tid < 128) {
        sA[0][f4 * 4 + 0][r] = ra.x; sA[0][f4 * 4 + 1][r] = ra.y;
        sA[0][f4 * 4 + 2][r] = ra.z; sA[0][f4 * 4 + 3][r] = ra.w;
    }
    sB[0][f4 * 4 + 0][r] = rb.x; sB[0][f4 * 4 + 1][r] = rb.y;
    sB[0][f4 * 4 + 2][r] = rb.z; sB[0][f4 * 4 + 3][r] = rb.w;
    __syncthreads();

    #pragma unroll
    for (int it = 0; it < 16; it++) {
        int cb = it & 1;
        if (it < 15) {
            int k0 = (it + 1) * 16;
            if (tid < 128) ra = *(const float4*)(A + (size_t)(m0 + r) * 256 + k0 + f4 * 4);
            rb = *(const float4*)(Wb + (size_t)(n0 + r) * 512 + k0 + f4 * 4);
        }
        #pragma unroll
        for (int k = 0; k < 16; k++) {
            float2 a = *(const float2*)&sA[cb][k][ty * 2];
            float4 bv = *(const float4*)&sB[cb][k][tx * 4];
            acc[0][0] = fmaf(a.x, bv.x, acc[0][0]); acc[0][1] = fmaf(a.x, bv.y, acc[0][1]);
            acc[0][2] = fmaf(a.x, bv.z, acc[0][2]); acc[0][3] = fmaf(a.x, bv.w, acc[0][3]);
            acc[1][0] = fmaf(a.y, bv.x, acc[1][0]); acc[1][1] = fmaf(a.y, bv.y, acc[1][1]);
            acc[1][2] = fmaf(a.y, bv.z, acc[1][2]); acc[1][3] = fmaf(a.y, bv.w, acc[1][3]);
        }
        if (it < 15) {
            int nb = cb ^ 1;
            if (tid < 128) {
                sA[nb][f4 * 4 + 0][r] = ra.x; sA[nb][f4 * 4 + 1][r] = ra.y;
                sA[nb][f4 * 4 + 2][r] = ra.z; sA[nb][f4 * 4 + 3][r] = ra.w;
            }
            sB[nb][f4 * 4 + 0][r] = rb.x; sB[nb][f4 * 4 + 1][r] = rb.y;
            sB[nb][f4 * 4 + 2][r] = rb.z; sB[nb][f4 * 4 + 3][r] = rb.w;
        }
        __syncthreads();
    }
    float* out = g_WdP[z];
    #pragma unroll
    for (int i = 0; i < 2; i++) {
        int m = m0 + ty * 2 + i;
        #pragma unroll
        for (int j = 0; j < 4; j++)
            out[m * 256 + n0 + tx * 4 + j] = acc[i][j];
    }
}

// ---------------- merged attention + gates GEMM ------------------------------
// blocks [0,1024): attention for batch b. blocks [1024,1280): gates tiles
// (64x64, M=N=1024, K=256, double-buffered). One launch -> HW co-schedules.
__global__ __launch_bounds__(256) void k_attn_gates(
    const float* __restrict__ Wvd, const float* __restrict__ bvd,
    const float* __restrict__ bdhs,
    const float* __restrict__ Ww,  const float* __restrict__ bw,
    const float* __restrict__ yhist, int step,
    const float* __restrict__ Whh, const float* __restrict__ bih,
    const float* __restrict__ bhh, int cur)
{
    __shared__ union {
        struct {
            float wd[256], wv[256], sc[128], part[8], bcast;
            float red[8][260];
        } at;
        struct {
            float A[2][16][68];
            float B[2][16][68];
        } gm;
    } sm;

    int tid = threadIdx.x;

    if (blockIdx.x >= 1024) {
        // ----- gates GEMM tile -----
        int bx2 = blockIdx.x - 1024;
        int m0 = (bx2 >> 4) * 64, n0 = (bx2 & 15) * 64;
        int tx = tid & 15, ty = tid >> 4;
        int r = tid >> 2, f4 = tid & 3;
        const float* A = g_h[cur];
        float acc[4][4] = {};
        float4 ra, rb;

        ra = *(const float4*)(A + (size_t)(m0 + r) * 256 + f4 * 4);
        rb = *(const float4*)(Whh + (size_t)(n0 + r) * 256 + f4 * 4);
        sm.gm.A[0][f4 * 4 + 0][r] = ra.x; sm.gm.A[0][f4 * 4 + 1][r] = ra.y;
        sm.gm.A[0][f4 * 4 + 2][r] = ra.z; sm.gm.A[0][f4 * 4 + 3][r] = ra.w;
        sm.gm.B[0][f4 * 4 + 0][r] = rb.x; sm.gm.B[0][f4 * 4 + 1][r] = rb.y;
        sm.gm.B[0][f4 * 4 + 2][r] = rb.z; sm.gm.B[0][f4 * 4 + 3][r] = rb.w;
        __syncthreads();

        #pragma unroll
        for (int it = 0; it < 16; it++) {
            int cb = it & 1;
            if (it < 15) {
                int k0 = (it + 1) * 16;
                ra = *(const float4*)(A + (size_t)(m0 + r) * 256 + k0 + f4 * 4);
                rb = *(const float4*)(Whh + (size_t)(n0 + r) * 256 + k0 + f4 * 4);
            }
            #pragma unroll
            for (int k = 0; k < 16; k++) {
                float4 a = *(const float4*)&sm.gm.A[cb][k][ty * 4];
                float am[4] = {a.x, a.y, a.z, a.w};
                float4 bv = *(const float4*)&sm.gm.B[cb][k][tx * 4];
                #pragma unroll
                for (int i = 0; i < 4; i++) {
                    acc[i][0] = fmaf(am[i], bv.x, acc[i][0]);
                    acc[i][1] = fmaf(am[i], bv.y, acc[i][1]);
                    acc[i][2] = fmaf(am[i], bv.z, acc[i][2]);
                    acc[i][3] = fmaf(am[i], bv.w, acc[i][3]);
                }
            }
            if (it < 15) {
                int nb = cb ^ 1;
                sm.gm.A[nb][f4 * 4 + 0][r] = ra.x; sm.gm.A[nb][f4 * 4 + 1][r] = ra.y;
                sm.gm.A[nb][f4 * 4 + 2][r] = ra.z; sm.gm.A[nb][f4 * 4 + 3][r] = ra.w;
                sm.gm.B[nb][f4 * 4 + 0][r] = rb.x; sm.gm.B[nb][f4 * 4 + 1][r] = rb.y;
                sm.gm.B[nb][f4 * 4 + 2][r] = rb.z; sm.gm.B[nb][f4 * 4 + 3][r] = rb.w;
            }
            __syncthreads();
        }
        #pragma unroll
        for (int i = 0; i < 4; i++) {
            int m = m0 + ty * 4 + i;
            #pragma unroll
            for (int j = 0; j < 4; j++) {
                int n = n0 + tx * 4 + j;
                g_gates[(size_t)m * 1024 + n] = acc[i][j] + bih[n] + bhh[n];
            }
        }
        return;
    }

    // ----- attention path -----
    int b = blockIdx.x;
    int lane = tid & 31, warp = tid >> 5;

    sm.at.wd[tid] = g_WdP[0][b * 256 + tid] + g_WdP[1][b * 256 + tid] + bdhs[tid];
    sm.at.wv[tid] = Wvd[tid];
    __syncthreads();

    const __half* ue = g_Ueh + (size_t)b * T * ENC;
    float bv = bvd[0];

    #pragma unroll 4
    for (int t = warp; t < T; t += 8) {
        float4 raw = *(const float4*)(ue + t * 256 + lane * 8);
        const __half2* hp = (const __half2*)&raw;
        int e0 = lane * 8;
        float acc = 0.f;
        #pragma unroll
        for (int j = 0; j < 4; j++) {
            float2 f = __half22float2(hp[j]);
            acc = fmaf(tanh_fast(sm.at.wd[e0 + 2 * j] + f.x),     sm.at.wv[e0 + 2 * j],     acc);
            acc = fmaf(tanh_fast(sm.at.wd[e0 + 2 * j + 1] + f.y), sm.at.wv[e0 + 2 * j + 1], acc);
        }
        #pragma unroll
        for (int o = 16; o; o >>= 1) acc += __shfl_xor_sync(0xffffffffu, acc, o);
        if (lane == 0) sm.at.sc[t] = acc + bv;
    }
    __syncthreads();

    float v = (tid < T) ? sm.at.sc[tid] : -3.4e38f;
    float m = v;
    #pragma unroll
    for (int o = 16; o; o >>= 1) m = fmaxf(m, __shfl_xor_sync(0xffffffffu, m, o));
    if (lane == 0) sm.at.part[warp] = m;
    __syncthreads();
    if (tid == 0) {
        float mm = sm.at.part[0];
        #pragma unroll
        for (int i = 1; i < 8; i++) mm = fmaxf(mm, sm.at.part[i]);
        sm.at.bcast = mm;
    }
    __syncthreads();
    float mx = sm.at.bcast;
    float ev = (tid < T) ? __expf(v - mx) : 0.f;
    if (tid < T) sm.at.sc[tid] = ev;
    float sum = ev;
    #pragma unroll
    for (int o = 16; o; o >>= 1) sum += __shfl_xor_sync(0xffffffffu, sum, o);
    if (lane == 0) sm.at.part[warp] = sum;
    __syncthreads();
    if (tid == 0) {
        float ss = 0.f;
        #pragma unroll
        for (int i = 0; i < 8; i++) ss += sm.at.part[i];
        sm.at.bcast = ss;
    }
    __syncthreads();
    float inv = 1.f / sm.at.bcast;

    int ch = tid & 31, tg = tid >> 5, e0 = ch * 8;
    const __half* xb = g_Xh + (size_t)b * T * ENC;
    float acc[8] = {};
    #pragma unroll 4
    for (int t = tg; t < T; t += 8) {
        float beta = sm.at.sc[t];
        float4 raw = *(const float4*)(xb + t * 256 + e0);
        const __half2* hp = (const __half2*)&raw;
        #pragma unroll
        for (int j = 0; j < 4; j++) {
            float2 f = __half22float2(hp[j]);
            acc[2 * j]     = fmaf(beta, f.x, acc[2 * j]);
            acc[2 * j + 1] = fmaf(beta, f.y, acc[2 * j + 1]);
        }
    }
    #pragma unroll
    for (int j = 0; j < 8; j++) sm.at.red[tg][e0 + j] = acc[j];
    __syncthreads();
    float cv = 0.f;
    #pragma unroll
    for (int g = 0; g < 8; g++) cv += sm.at.red[g][tid];
    cv *= inv;
    g_ctx[b * 256 + tid] = cv;

    float yv = cv * Ww[tid];
    #pragma unroll
    for (int o = 16; o; o >>= 1) yv += __shfl_xor_sync(0xffffffffu, yv, o);
    if (lane == 0) sm.at.part[warp] = yv;
    __syncthreads();
    if (tid == 0) {
        float ss = 0.f;
        #pragma unroll
        for (int i = 0; i < 8; i++) ss += sm.at.part[i];
        g_yt[b] = ss + yhist[b * T + step] * Ww[256] + bw[0];
    }
}

// ---------------- LSTM cell elementwise --------------------------------------
__global__ __launch_bounds__(256) void k_cell(const float* __restrict__ Wih, int cur)
{
    int idx = blockIdx.x * 256 + threadIdx.x;
    int b = idx >> 8, d = idx & 255;
    float yt = g_yt[b];
    const float* gb = g_gates + (size_t)b * 1024;
    float gi = gb[d]       + yt * Wih[d];
    float gf = gb[256 + d] + yt * Wih[256 + d];
    float gg = gb[512 + d] + yt * Wih[512 + d];
    float go = gb[768 + d] + yt * Wih[768 + d];
    float ig = 1.f / (1.f + expf(-gi));
    float fg = 1.f / (1.f + expf(-gf));
    float gt = tanhf(gg);
    float og = 1.f / (1.f + expf(-go));
    int nxt = cur ^ 1;
    float cn = fg * g_c[cur][idx] + ig * gt;
    g_c[nxt][idx] = cn;
    g_h[nxt][idx] = og * tanhf(cn);
}

// ---------------- final projection -------------------------------------------
__global__ __launch_bounds__(256) void k_final(
    const float* __restrict__ Wfc, const float* __restrict__ bfc,
    float* __restrict__ out, int fin)
{
    int b = blockIdx.x, tid = threadIdx.x, lane = tid & 31, warp = tid >> 5;
    __shared__ float s_part[8];
    float v = g_h[fin][b * 256 + tid] * Wfc[tid]
            + g_ctx[b * 256 + tid] * Wfc[256 + tid];
    #pragma unroll
    for (int o = 16; o; o >>= 1) v += __shfl_xor_sync(0xffffffffu, v, o);
    if (lane == 0) s_part[warp] = v;
    __syncthreads();
    if (tid == 0) {
        float ss = 0.f;
        #pragma unroll
        for (int i = 0; i < 8; i++) ss += s_part[i];
        out[b] = ss + bfc[0];
    }
}

// ---------------- host -------------------------------------------------------
extern "C" void kernel_launch(void* const* d_in, const int* in_sizes, int n_in,
                              void* d_out, int out_size)
{
    const float* X     = (const float*)d_in[0];
    const float* yhist = (const float*)d_in[1];
    const float* W_vd  = (const float*)d_in[2];
    const float* b_vd  = (const float*)d_in[3];
    const float* W_dhs = (const float*)d_in[4];
    const float* b_dhs = (const float*)d_in[5];
    const float* W_Ud  = (const float*)d_in[6];
    const float* b_Ud  = (const float*)d_in[7];
    const float* W_w   = (const float*)d_in[8];
    const float* b_w   = (const float*)d_in[9];
    const float* W_ih  = (const float*)d_in[10];
    const float* W_hh  = (const float*)d_in[11];
    const float* b_ih  = (const float*)d_in[12];
    const float* b_hh  = (const float*)d_in[13];
    const float* W_fc  = (const float*)d_in[14];
    const float* b_fc  = (const float*)d_in[15];
    float* out = (float*)d_out;

    k_zero_state<<<(BATCH * DEC) / 256, 256>>>();
    {
        dim3 grid(ENC / 64, (BATCH * T) / 128);
        k_gemm_ue<<<grid, 256>>>(X, W_Ud, b_Ud);
    }

    for (int s = 0; s < T; s++) {
        int cur = s & 1;
        {
            dim3 grid(ENC / 64, BATCH / 32, 2);
            k_wd<<<grid, 256>>>(W_dhs, cur);
        }
        k_attn_gates<<<1024 + 256, 256>>>(W_vd, b_vd, b_dhs, W_w, b_w, yhist, s,
                                          W_hh, b_ih, b_hh, cur);
        k_cell<<<(BATCH * DEC) / 256, 256>>>(W_ih, cur);
    }

    k_final<<<BATCH, 256>>>(W_fc, b_fc, out, T & 1);
}

// round 8
// speedup vs baseline: 2.3251x; 1.1743x over previous
#include <cuda_runtime.h>
#include <cuda_fp16.h>
#include <math.h>

#define BATCH 1024
#define T     127
#define ENC   256
#define DEC   256

// ---------------- scratch (device globals) ----------------------------------
__device__ __half g_Ueh[(size_t)BATCH * T * ENC];   // 66.6 MB
__device__ __half g_Xh[(size_t)BATCH * T * ENC];    // 66.6 MB
__device__ float  g_h[2][BATCH * DEC];
__device__ float  g_c[2][BATCH * DEC];
__device__ float  g_WdP[2][BATCH * ENC];            // split-K partials
__device__ float  g_gates[(size_t)BATCH * 4 * DEC];
__device__ float  g_ctx[BATCH * ENC];
__device__ float  g_yt[BATCH];

// fast f16x2 tanh: use the cuda_fp16.hpp intrinsic (tanh.approx.f16x2)
__device__ __forceinline__ __half2 fast_tanh2(__half2 x) {
    return h2tanh_approx(x);
}

// ---------------- init ------------------------------------------------------
__global__ void k_zero_state() {
    int i = blockIdx.x * 256 + threadIdx.x;
    g_h[0][i] = 0.f;
    g_c[0][i] = 0.f;
}

// ---------------- Ue GEMM (+ fused X->half convert on n-tile 0) --------------
__global__ __launch_bounds__(256) void k_gemm_ue(
    const float* __restrict__ X, const float* __restrict__ W,
    const float* __restrict__ bias)
{
    __shared__ float sA[16][132];
    __shared__ float sB[16][68];
    int tid = threadIdx.x;
    int m0 = blockIdx.y * 128;
    int n0 = blockIdx.x * 64;
    int tx = tid & 15, ty = tid >> 4;
    bool cvt = (blockIdx.x == 0);
    float acc[8][4] = {};

    for (int k0 = 0; k0 < 256; k0 += 16) {
        #pragma unroll
        for (int i = 0; i < 2; i++) {
            int lin = tid + i * 256;
            int r = lin >> 2, f4 = lin & 3;
            size_t off = (size_t)(m0 + r) * 256 + k0 + f4 * 4;
            float4 v = *(const float4*)(X + off);
            sA[f4 * 4 + 0][r] = v.x; sA[f4 * 4 + 1][r] = v.y;
            sA[f4 * 4 + 2][r] = v.z; sA[f4 * 4 + 3][r] = v.w;
            if (cvt) {
                __half2* dst = (__half2*)(g_Xh + off);
                dst[0] = __floats2half2_rn(v.x, v.y);
                dst[1] = __floats2half2_rn(v.z, v.w);
            }
        }
        {
            int r = tid >> 2, f4 = tid & 3;
            float4 v = *(const float4*)(W + (size_t)(n0 + r) * 256 + k0 + f4 * 4);
            sB[f4 * 4 + 0][r] = v.x; sB[f4 * 4 + 1][r] = v.y;
            sB[f4 * 4 + 2][r] = v.z; sB[f4 * 4 + 3][r] = v.w;
        }
        __syncthreads();
        #pragma unroll
        for (int k = 0; k < 16; k++) {
            float a[8];
            #pragma unroll
            for (int i = 0; i < 8; i++) a[i] = sA[k][ty * 8 + i];
            float4 bv = *(const float4*)&sB[k][tx * 4];
            #pragma unroll
            for (int i = 0; i < 8; i++) {
                acc[i][0] = fmaf(a[i], bv.x, acc[i][0]);
                acc[i][1] = fmaf(a[i], bv.y, acc[i][1]);
                acc[i][2] = fmaf(a[i], bv.z, acc[i][2]);
                acc[i][3] = fmaf(a[i], bv.w, acc[i][3]);
            }
        }
        __syncthreads();
    }
    float b0 = bias[n0 + tx * 4], b1 = bias[n0 + tx * 4 + 1];
    float b2 = bias[n0 + tx * 4 + 2], b3 = bias[n0 + tx * 4 + 3];
    #pragma unroll
    for (int i = 0; i < 8; i++) {
        size_t m = m0 + ty * 8 + i;
        __half2* dst = (__half2*)(g_Ueh + m * 256 + n0 + tx * 4);
        dst[0] = __floats2half2_rn(acc[i][0] + b0, acc[i][1] + b1);
        dst[1] = __floats2half2_rn(acc[i][2] + b2, acc[i][3] + b3);
    }
}

// ---------------- merged Wd split-K + gates GEMM -----------------------------
// blocks [0,256): Wd 32x64 tiles (bid&3 = n-tile, (bid>>2)&31 = m-tile,
//                 bid>>7 = z picks h/c half of K). double-buffered.
// blocks [256,512): gates 64x64 tiles (M=N=1024, K=256). double-buffered.
__global__ __launch_bounds__(256) void k_wd_gates(
    const float* __restrict__ Wdhs,
    const float* __restrict__ Whh, const float* __restrict__ bih,
    const float* __restrict__ bhh, int cur)
{
    __shared__ union {
        struct { float A[2][16][36]; float B[2][16][68]; } wd;
        struct { float A[2][16][68]; float B[2][16][68]; } gm;
    } sm;
    int tid = threadIdx.x;
    int tx = tid & 15, ty = tid >> 4;
    int r = tid >> 2, f4 = tid & 3;

    if (blockIdx.x < 256) {
        // ---- Wd tile ----
        int bid = blockIdx.x;
        int z = bid >> 7;
        int m0 = ((bid >> 2) & 31) * 32, n0 = (bid & 3) * 64;
        const float* A = z ? g_c[cur] : g_h[cur];
        const float* Wb = Wdhs + z * 256;       // row stride 512
        float acc[2][4] = {};
        float4 ra, rb;

        if (tid < 128) ra = *(const float4*)(A + (size_t)(m0 + r) * 256 + f4 * 4);
        rb = *(const float4*)(Wb + (size_t)(n0 + r) * 512 + f4 * 4);
        if (tid < 128) {
            sm.wd.A[0][f4 * 4 + 0][r] = ra.x; sm.wd.A[0][f4 * 4 + 1][r] = ra.y;
            sm.wd.A[0][f4 * 4 + 2][r] = ra.z; sm.wd.A[0][f4 * 4 + 3][r] = ra.w;
        }
        sm.wd.B[0][f4 * 4 + 0][r] = rb.x; sm.wd.B[0][f4 * 4 + 1][r] = rb.y;
        sm.wd.B[0][f4 * 4 + 2][r] = rb.z; sm.wd.B[0][f4 * 4 + 3][r] = rb.w;
        __syncthreads();

        #pragma unroll
        for (int it = 0; it < 16; it++) {
            int cb = it & 1;
            if (it < 15) {
                int k0 = (it + 1) * 16;
                if (tid < 128) ra = *(const float4*)(A + (size_t)(m0 + r) * 256 + k0 + f4 * 4);
                rb = *(const float4*)(Wb + (size_t)(n0 + r) * 512 + k0 + f4 * 4);
            }
            #pragma unroll
            for (int k = 0; k < 16; k++) {
                float2 a = *(const float2*)&sm.wd.A[cb][k][ty * 2];
                float4 bv = *(const float4*)&sm.wd.B[cb][k][tx * 4];
                acc[0][0] = fmaf(a.x, bv.x, acc[0][0]); acc[0][1] = fmaf(a.x, bv.y, acc[0][1]);
                acc[0][2] = fmaf(a.x, bv.z, acc[0][2]); acc[0][3] = fmaf(a.x, bv.w, acc[0][3]);
                acc[1][0] = fmaf(a.y, bv.x, acc[1][0]); acc[1][1] = fmaf(a.y, bv.y, acc[1][1]);
                acc[1][2] = fmaf(a.y, bv.z, acc[1][2]); acc[1][3] = fmaf(a.y, bv.w, acc[1][3]);
            }
            if (it < 15) {
                int nb = cb ^ 1;
                if (tid < 128) {
                    sm.wd.A[nb][f4 * 4 + 0][r] = ra.x; sm.wd.A[nb][f4 * 4 + 1][r] = ra.y;
                    sm.wd.A[nb][f4 * 4 + 2][r] = ra.z; sm.wd.A[nb][f4 * 4 + 3][r] = ra.w;
                }
                sm.wd.B[nb][f4 * 4 + 0][r] = rb.x; sm.wd.B[nb][f4 * 4 + 1][r] = rb.y;
                sm.wd.B[nb][f4 * 4 + 2][r] = rb.z; sm.wd.B[nb][f4 * 4 + 3][r] = rb.w;
            }
            __syncthreads();
        }
        float* outp = g_WdP[z];
        #pragma unroll
        for (int i = 0; i < 2; i++) {
            int m = m0 + ty * 2 + i;
            #pragma unroll
            for (int j = 0; j < 4; j++)
                outp[m * 256 + n0 + tx * 4 + j] = acc[i][j];
        }
        return;
    }

    // ---- gates tile ----
    int bx2 = blockIdx.x - 256;
    int m0 = (bx2 >> 4) * 64, n0 = (bx2 & 15) * 64;
    const float* A = g_h[cur];
    float acc[4][4] = {};
    float4 ra, rb;

    ra = *(const float4*)(A + (size_t)(m0 + r) * 256 + f4 * 4);
    rb = *(const float4*)(Whh + (size_t)(n0 + r) * 256 + f4 * 4);
    sm.gm.A[0][f4 * 4 + 0][r] = ra.x; sm.gm.A[0][f4 * 4 + 1][r] = ra.y;
    sm.gm.A[0][f4 * 4 + 2][r] = ra.z; sm.gm.A[0][f4 * 4 + 3][r] = ra.w;
    sm.gm.B[0][f4 * 4 + 0][r] = rb.x; sm.gm.B[0][f4 * 4 + 1][r] = rb.y;
    sm.gm.B[0][f4 * 4 + 2][r] = rb.z; sm.gm.B[0][f4 * 4 + 3][r] = rb.w;
    __syncthreads();

    #pragma unroll
    for (int it = 0; it < 16; it++) {
        int cb = it & 1;
        if (it < 15) {
            int k0 = (it + 1) * 16;
            ra = *(const float4*)(A + (size_t)(m0 + r) * 256 + k0 + f4 * 4);
            rb = *(const float4*)(Whh + (size_t)(n0 + r) * 256 + k0 + f4 * 4);
        }
        #pragma unroll
        for (int k = 0; k < 16; k++) {
            float4 a = *(const float4*)&sm.gm.A[cb][k][ty * 4];
            float am[4] = {a.x, a.y, a.z, a.w};
            float4 bv = *(const float4*)&sm.gm.B[cb][k][tx * 4];
            #pragma unroll
            for (int i = 0; i < 4; i++) {
                acc[i][0] = fmaf(am[i], bv.x, acc[i][0]);
                acc[i][1] = fmaf(am[i], bv.y, acc[i][1]);
                acc[i][2] = fmaf(am[i], bv.z, acc[i][2]);
                acc[i][3] = fmaf(am[i], bv.w, acc[i][3]);
            }
        }
        if (it < 15) {
            int nb = cb ^ 1;
            sm.gm.A[nb][f4 * 4 + 0][r] = ra.x; sm.gm.A[nb][f4 * 4 + 1][r] = ra.y;
            sm.gm.A[nb][f4 * 4 + 2][r] = ra.z; sm.gm.A[nb][f4 * 4 + 3][r] = ra.w;
            sm.gm.B[nb][f4 * 4 + 0][r] = rb.x; sm.gm.B[nb][f4 * 4 + 1][r] = rb.y;
            sm.gm.B[nb][f4 * 4 + 2][r] = rb.z; sm.gm.B[nb][f4 * 4 + 3][r] = rb.w;
        }
        __syncthreads();
    }
    #pragma unroll
    for (int i = 0; i < 4; i++) {
        int m = m0 + ty * 4 + i;
        #pragma unroll
        for (int j = 0; j < 4; j++) {
            int n = n0 + tx * 4 + j;
            g_gates[(size_t)m * 1024 + n] = acc[i][j] + bih[n] + bhh[n];
        }
    }
}

// ---------------- fused attention step (half2 tanh pipeline) -----------------
__global__ __launch_bounds__(256) void k_attn(
    const float* __restrict__ Wvd, const float* __restrict__ bvd,
    const float* __restrict__ bdhs,
    const float* __restrict__ Ww,  const float* __restrict__ bw,
    const float* __restrict__ yhist, int step)
{
    int b = blockIdx.x;
    int tid = threadIdx.x, lane = tid & 31, warp = tid >> 5;
    __shared__ float s_wdf[256];
    __shared__ float s_sc[128];
    __shared__ float s_part[8];
    __shared__ float s_bcast;
    __shared__ float s_red[8][264];

    s_wdf[tid] = g_WdP[0][b * 256 + tid] + g_WdP[1][b * 256 + tid] + bdhs[tid];
    __syncthreads();

    // per-lane register preload: Wd as half2 x4, Wv as float x8 (e = lane*8..+7)
    int e0 = lane * 8;
    __half2 wdh[4];
    float wvr[8];
    #pragma unroll
    for (int j = 0; j < 4; j++)
        wdh[j] = __floats2half2_rn(s_wdf[e0 + 2 * j], s_wdf[e0 + 2 * j + 1]);
    #pragma unroll
    for (int j = 0; j < 8; j++) wvr[j] = Wvd[e0 + j];

    const __half* ue = g_Ueh + (size_t)b * T * ENC;
    float bv = bvd[0];

    // scores[t] = sum_e tanh(Wd[e]+Ue[t,e]) * Wv[e] + bv
    #pragma unroll 4
    for (int t = warp; t < T; t += 8) {
        float4 raw = *(const float4*)(ue + t * 256 + e0);
        const __half2* hp = (const __half2*)&raw;
        float acc = 0.f;
        #pragma unroll
        for (int j = 0; j < 4; j++) {
            __half2 th = fast_tanh2(__hadd2(wdh[j], hp[j]));
            float2 f = __half22float2(th);
            acc = fmaf(f.x, wvr[2 * j],     acc);
            acc = fmaf(f.y, wvr[2 * j + 1], acc);
        }
        #pragma unroll
        for (int o = 16; o; o >>= 1) acc += __shfl_xor_sync(0xffffffffu, acc, o);
        if (lane == 0) s_sc[t] = acc + bv;
    }
    __syncthreads();

    // softmax (no max pass: |score| <= ~8, exp safe in fp32)
    float ev = (tid < T) ? __expf(s_sc[tid]) : 0.f;
    if (tid < T) s_sc[tid] = ev;
    float sum = ev;
    #pragma unroll
    for (int o = 16; o; o >>= 1) sum += __shfl_xor_sync(0xffffffffu, sum, o);
    if (lane == 0) s_part[warp] = sum;
    __syncthreads();
    if (tid == 0) {
        float ss = 0.f;
        #pragma unroll
        for (int i = 0; i < 8; i++) ss += s_part[i];
        s_bcast = ss;
    }
    __syncthreads();
    float inv = 1.f / s_bcast;

    // context: thread = (e-chunk of 8, t-group of 8); 16B loads
    int tg = tid >> 5;
    const __half* xb = g_Xh + (size_t)b * T * ENC;
    float acc[8] = {};
    #pragma unroll 4
    for (int t = tg; t < T; t += 8) {
        float beta = s_sc[t];
        float4 raw = *(const float4*)(xb + t * 256 + e0);
        const __half2* hp = (const __half2*)&raw;
        #pragma unroll
        for (int j = 0; j < 4; j++) {
            float2 f = __half22float2(hp[j]);
            acc[2 * j]     = fmaf(beta, f.x, acc[2 * j]);
            acc[2 * j + 1] = fmaf(beta, f.y, acc[2 * j + 1]);
        }
    }
    #pragma unroll
    for (int j = 0; j < 8; j++) s_red[tg][e0 + j] = acc[j];
    __syncthreads();
    float cv = 0.f;
    #pragma unroll
    for (int g = 0; g < 8; g++) cv += s_red[g][tid];
    cv *= inv;
    g_ctx[b * 256 + tid] = cv;

    // y_tilde
    float yv = cv * Ww[tid];
    #pragma unroll
    for (int o = 16; o; o >>= 1) yv += __shfl_xor_sync(0xffffffffu, yv, o);
    if (lane == 0) s_part[warp] = yv;
    __syncthreads();
    if (tid == 0) {
        float ss = 0.f;
        #pragma unroll
        for (int i = 0; i < 8; i++) ss += s_part[i];
        g_yt[b] = ss + yhist[b * T + step] * Ww[256] + bw[0];
    }
}

// ---------------- LSTM cell elementwise --------------------------------------
__global__ __launch_bounds__(256) void k_cell(const float* __restrict__ Wih, int cur)
{
    int idx = blockIdx.x * 256 + threadIdx.x;
    int b = idx >> 8, d = idx & 255;
    float yt = g_yt[b];
    const float* gb = g_gates + (size_t)b * 1024;
    float gi = gb[d]       + yt * Wih[d];
    float gf = gb[256 + d] + yt * Wih[256 + d];
    float gg = gb[512 + d] + yt * Wih[512 + d];
    float go = gb[768 + d] + yt * Wih[768 + d];
    float ig = 1.f / (1.f + expf(-gi));
    float fg = 1.f / (1.f + expf(-gf));
    float gt = tanhf(gg);
    float og = 1.f / (1.f + expf(-go));
    int nxt = cur ^ 1;
    float cn = fg * g_c[cur][idx] + ig * gt;
    g_c[nxt][idx] = cn;
    g_h[nxt][idx] = og * tanhf(cn);
}

// ---------------- final projection -------------------------------------------
__global__ __launch_bounds__(256) void k_final(
    const float* __restrict__ Wfc, const float* __restrict__ bfc,
    float* __restrict__ out, int fin)
{
    int b = blockIdx.x, tid = threadIdx.x, lane = tid & 31, warp = tid >> 5;
    __shared__ float s_part[8];
    float v = g_h[fin][b * 256 + tid] * Wfc[tid]
            + g_ctx[b * 256 + tid] * Wfc[256 + tid];
    #pragma unroll
    for (int o = 16; o; o >>= 1) v += __shfl_xor_sync(0xffffffffu, v, o);
    if (lane == 0) s_part[warp] = v;
    __syncthreads();
    if (tid == 0) {
        float ss = 0.f;
        #pragma unroll
        for (int i = 0; i < 8; i++) ss += s_part[i];
        out[b] = ss + bfc[0];
    }
}

// ---------------- host -------------------------------------------------------
extern "C" void kernel_launch(void* const* d_in, const int* in_sizes, int n_in,
                              void* d_out, int out_size)
{
    const float* X     = (const float*)d_in[0];
    const float* yhist = (const float*)d_in[1];
    const float* W_vd  = (const float*)d_in[2];
    const float* b_vd  = (const float*)d_in[3];
    const float* W_dhs = (const float*)d_in[4];
    const float* b_dhs = (const float*)d_in[5];
    const float* W_Ud  = (const float*)d_in[6];
    const float* b_Ud  = (const float*)d_in[7];
    const float* W_w   = (const float*)d_in[8];
    const float* b_w   = (const float*)d_in[9];
    const float* W_ih  = (const float*)d_in[10];
    const float* W_hh  = (const float*)d_in[11];
    const float* b_ih  = (const float*)d_in[12];
    const float* b_hh  = (const float*)d_in[13];
    const float* W_fc  = (const float*)d_in[14];
    const float* b_fc  = (const float*)d_in[15];
    float* out = (float*)d_out;

    k_zero_state<<<(BATCH * DEC) / 256, 256>>>();
    {
        dim3 grid(ENC / 64, (BATCH * T) / 128);
        k_gemm_ue<<<grid, 256>>>(X, W_Ud, b_Ud);
    }

    for (int s = 0; s < T; s++) {
        int cur = s & 1;
        k_wd_gates<<<512, 256>>>(W_dhs, W_hh, b_ih, b_hh, cur);
        k_attn<<<BATCH, 256>>>(W_vd, b_vd, b_dhs, W_w, b_w, yhist, s);
        k_cell<<<(BATCH * DEC) / 256, 256>>>(W_ih, cur);
    }

    k_final<<<BATCH, 256>>>(W_fc, b_fc, out, T & 1);
}

// round 9
// speedup vs baseline: 2.3599x; 1.0150x over previous
#include <cuda_runtime.h>
#include <cuda_fp16.h>
#include <math.h>

#define BATCH 1024
#define T     127
#define ENC   256
#define DEC   256

// ---------------- scratch (device globals) ----------------------------------
__device__ __half g_Ueh[(size_t)BATCH * T * ENC];   // 66.6 MB
__device__ __half g_Xh[(size_t)BATCH * T * ENC];    // 66.6 MB
__device__ float  g_h[2][BATCH * DEC];
__device__ float  g_c[2][BATCH * DEC];
__device__ float  g_WdP[2][BATCH * ENC];            // split-K partials
__device__ float  g_gates[(size_t)BATCH * 4 * DEC];
__device__ float  g_ctx[BATCH * ENC];

// fast f16x2 tanh: cuda_fp16.hpp intrinsic (tanh.approx.f16x2)
__device__ __forceinline__ __half2 fast_tanh2(__half2 x) {
    return h2tanh_approx(x);
}

// ---------------- init ------------------------------------------------------
__global__ void k_zero_state() {
    int i = blockIdx.x * 256 + threadIdx.x;
    g_h[0][i] = 0.f;
    g_c[0][i] = 0.f;
}

// ---------------- Ue GEMM (+ fused X->half convert on n-tile 0) --------------
__global__ __launch_bounds__(256) void k_gemm_ue(
    const float* __restrict__ X, const float* __restrict__ W,
    const float* __restrict__ bias)
{
    __shared__ float sA[16][132];
    __shared__ float sB[16][68];
    int tid = threadIdx.x;
    int m0 = blockIdx.y * 128;
    int n0 = blockIdx.x * 64;
    int tx = tid & 15, ty = tid >> 4;
    bool cvt = (blockIdx.x == 0);
    float acc[8][4] = {};

    for (int k0 = 0; k0 < 256; k0 += 16) {
        #pragma unroll
        for (int i = 0; i < 2; i++) {
            int lin = tid + i * 256;
            int r = lin >> 2, f4 = lin & 3;
            size_t off = (size_t)(m0 + r) * 256 + k0 + f4 * 4;
            float4 v = *(const float4*)(X + off);
            sA[f4 * 4 + 0][r] = v.x; sA[f4 * 4 + 1][r] = v.y;
            sA[f4 * 4 + 2][r] = v.z; sA[f4 * 4 + 3][r] = v.w;
            if (cvt) {
                __half2* dst = (__half2*)(g_Xh + off);
                dst[0] = __floats2half2_rn(v.x, v.y);
                dst[1] = __floats2half2_rn(v.z, v.w);
            }
        }
        {
            int r = tid >> 2, f4 = tid & 3;
            float4 v = *(const float4*)(W + (size_t)(n0 + r) * 256 + k0 + f4 * 4);
            sB[f4 * 4 + 0][r] = v.x; sB[f4 * 4 + 1][r] = v.y;
            sB[f4 * 4 + 2][r] = v.z; sB[f4 * 4 + 3][r] = v.w;
        }
        __syncthreads();
        #pragma unroll
        for (int k = 0; k < 16; k++) {
            float a[8];
            #pragma unroll
            for (int i = 0; i < 8; i++) a[i] = sA[k][ty * 8 + i];
            float4 bv = *(const float4*)&sB[k][tx * 4];
            #pragma unroll
            for (int i = 0; i < 8; i++) {
                acc[i][0] = fmaf(a[i], bv.x, acc[i][0]);
                acc[i][1] = fmaf(a[i], bv.y, acc[i][1]);
                acc[i][2] = fmaf(a[i], bv.z, acc[i][2]);
                acc[i][3] = fmaf(a[i], bv.w, acc[i][3]);
            }
        }
        __syncthreads();
    }
    float b0 = bias[n0 + tx * 4], b1 = bias[n0 + tx * 4 + 1];
    float b2 = bias[n0 + tx * 4 + 2], b3 = bias[n0 + tx * 4 + 3];
    #pragma unroll
    for (int i = 0; i < 8; i++) {
        size_t m = m0 + ty * 8 + i;
        __half2* dst = (__half2*)(g_Ueh + m * 256 + n0 + tx * 4);
        dst[0] = __floats2half2_rn(acc[i][0] + b0, acc[i][1] + b1);
        dst[1] = __floats2half2_rn(acc[i][2] + b2, acc[i][3] + b3);
    }
}

// ---------------- merged Wd split-K + gates GEMM -----------------------------
// blocks [0,256): Wd 32x64 tiles. blocks [256,512): gates 64x64 tiles.
__global__ __launch_bounds__(256) void k_wd_gates(
    const float* __restrict__ Wdhs,
    const float* __restrict__ Whh, const float* __restrict__ bih,
    const float* __restrict__ bhh, int cur)
{
    __shared__ union {
        struct { float A[2][16][36]; float B[2][16][68]; } wd;
        struct { float A[2][16][68]; float B[2][16][68]; } gm;
    } sm;
    int tid = threadIdx.x;
    int tx = tid & 15, ty = tid >> 4;
    int r = tid >> 2, f4 = tid & 3;

    if (blockIdx.x < 256) {
        // ---- Wd tile ----
        int bid = blockIdx.x;
        int z = bid >> 7;
        int m0 = ((bid >> 2) & 31) * 32, n0 = (bid & 3) * 64;
        const float* A = z ? g_c[cur] : g_h[cur];
        const float* Wb = Wdhs + z * 256;       // row stride 512
        float acc[2][4] = {};
        float4 ra, rb;

        if (tid < 128) ra = *(const float4*)(A + (size_t)(m0 + r) * 256 + f4 * 4);
        rb = *(const float4*)(Wb + (size_t)(n0 + r) * 512 + f4 * 4);
        if (tid < 128) {
            sm.wd.A[0][f4 * 4 + 0][r] = ra.x; sm.wd.A[0][f4 * 4 + 1][r] = ra.y;
            sm.wd.A[0][f4 * 4 + 2][r] = ra.z; sm.wd.A[0][f4 * 4 + 3][r] = ra.w;
        }
        sm.wd.B[0][f4 * 4 + 0][r] = rb.x; sm.wd.B[0][f4 * 4 + 1][r] = rb.y;
        sm.wd.B[0][f4 * 4 + 2][r] = rb.z; sm.wd.B[0][f4 * 4 + 3][r] = rb.w;
        __syncthreads();

        #pragma unroll
        for (int it = 0; it < 16; it++) {
            int cb = it & 1;
            if (it < 15) {
                int k0 = (it + 1) * 16;
                if (tid < 128) ra = *(const float4*)(A + (size_t)(m0 + r) * 256 + k0 + f4 * 4);
                rb = *(const float4*)(Wb + (size_t)(n0 + r) * 512 + k0 + f4 * 4);
            }
            #pragma unroll
            for (int k = 0; k < 16; k++) {
                float2 a = *(const float2*)&sm.wd.A[cb][k][ty * 2];
                float4 bv = *(const float4*)&sm.wd.B[cb][k][tx * 4];
                acc[0][0] = fmaf(a.x, bv.x, acc[0][0]); acc[0][1] = fmaf(a.x, bv.y, acc[0][1]);
                acc[0][2] = fmaf(a.x, bv.z, acc[0][2]); acc[0][3] = fmaf(a.x, bv.w, acc[0][3]);
                acc[1][0] = fmaf(a.y, bv.x, acc[1][0]); acc[1][1] = fmaf(a.y, bv.y, acc[1][1]);
                acc[1][2] = fmaf(a.y, bv.z, acc[1][2]); acc[1][3] = fmaf(a.y, bv.w, acc[1][3]);
            }
            if (it < 15) {
                int nb = cb ^ 1;
                if (tid < 128) {
                    sm.wd.A[nb][f4 * 4 + 0][r] = ra.x; sm.wd.A[nb][f4 * 4 + 1][r] = ra.y;
                    sm.wd.A[nb][f4 * 4 + 2][r] = ra.z; sm.wd.A[nb][f4 * 4 + 3][r] = ra.w;
                }
                sm.wd.B[nb][f4 * 4 + 0][r] = rb.x; sm.wd.B[nb][f4 * 4 + 1][r] = rb.y;
                sm.wd.B[nb][f4 * 4 + 2][r] = rb.z; sm.wd.B[nb][f4 * 4 + 3][r] = rb.w;
            }
            __syncthreads();
        }
        float* outp = g_WdP[z];
        #pragma unroll
        for (int i = 0; i < 2; i++) {
            int m = m0 + ty * 2 + i;
            #pragma unroll
            for (int j = 0; j < 4; j++)
                outp[m * 256 + n0 + tx * 4 + j] = acc[i][j];
        }
        return;
    }

    // ---- gates tile ----
    int bx2 = blockIdx.x - 256;
    int m0 = (bx2 >> 4) * 64, n0 = (bx2 & 15) * 64;
    const float* A = g_h[cur];
    float acc[4][4] = {};
    float4 ra, rb;

    ra = *(const float4*)(A + (size_t)(m0 + r) * 256 + f4 * 4);
    rb = *(const float4*)(Whh + (size_t)(n0 + r) * 256 + f4 * 4);
    sm.gm.A[0][f4 * 4 + 0][r] = ra.x; sm.gm.A[0][f4 * 4 + 1][r] = ra.y;
    sm.gm.A[0][f4 * 4 + 2][r] = ra.z; sm.gm.A[0][f4 * 4 + 3][r] = ra.w;
    sm.gm.B[0][f4 * 4 + 0][r] = rb.x; sm.gm.B[0][f4 * 4 + 1][r] = rb.y;
    sm.gm.B[0][f4 * 4 + 2][r] = rb.z; sm.gm.B[0][f4 * 4 + 3][r] = rb.w;
    __syncthreads();

    #pragma unroll
    for (int it = 0; it < 16; it++) {
        int cb = it & 1;
        if (it < 15) {
            int k0 = (it + 1) * 16;
            ra = *(const float4*)(A + (size_t)(m0 + r) * 256 + k0 + f4 * 4);
            rb = *(const float4*)(Whh + (size_t)(n0 + r) * 256 + k0 + f4 * 4);
        }
        #pragma unroll
        for (int k = 0; k < 16; k++) {
            float4 a = *(const float4*)&sm.gm.A[cb][k][ty * 4];
            float am[4] = {a.x, a.y, a.z, a.w};
            float4 bv = *(const float4*)&sm.gm.B[cb][k][tx * 4];
            #pragma unroll
            for (int i = 0; i < 4; i++) {
                acc[i][0] = fmaf(am[i], bv.x, acc[i][0]);
                acc[i][1] = fmaf(am[i], bv.y, acc[i][1]);
                acc[i][2] = fmaf(am[i], bv.z, acc[i][2]);
                acc[i][3] = fmaf(am[i], bv.w, acc[i][3]);
            }
        }
        if (it < 15) {
            int nb = cb ^ 1;
            sm.gm.A[nb][f4 * 4 + 0][r] = ra.x; sm.gm.A[nb][f4 * 4 + 1][r] = ra.y;
            sm.gm.A[nb][f4 * 4 + 2][r] = ra.z; sm.gm.A[nb][f4 * 4 + 3][r] = ra.w;
            sm.gm.B[nb][f4 * 4 + 0][r] = rb.x; sm.gm.B[nb][f4 * 4 + 1][r] = rb.y;
            sm.gm.B[nb][f4 * 4 + 2][r] = rb.z; sm.gm.B[nb][f4 * 4 + 3][r] = rb.w;
        }
        __syncthreads();
    }
    #pragma unroll
    for (int i = 0; i < 4; i++) {
        int m = m0 + ty * 4 + i;
        #pragma unroll
        for (int j = 0; j < 4; j++) {
            int n = n0 + tx * 4 + j;
            g_gates[(size_t)m * 1024 + n] = acc[i][j] + bih[n] + bhh[n];
        }
    }
}

// ---------------- fused attention + LSTM cell ---------------------------------
// block b: scores -> softmax -> context -> y_tilde -> cell update for row b.
__global__ __launch_bounds__(256) void k_attn_cell(
    const float* __restrict__ Wvd, const float* __restrict__ bvd,
    const float* __restrict__ bdhs,
    const float* __restrict__ Ww,  const float* __restrict__ bw,
    const float* __restrict__ yhist,
    const float* __restrict__ Wih, int step, int cur)
{
    int b = blockIdx.x;
    int tid = threadIdx.x, lane = tid & 31, warp = tid >> 5;
    __shared__ float s_wdf[256];
    __shared__ float s_sc[128];
    __shared__ float s_part[8];
    __shared__ float s_bcast;
    __shared__ float s_red[8][264];

    s_wdf[tid] = g_WdP[0][b * 256 + tid] + g_WdP[1][b * 256 + tid] + bdhs[tid];
    __syncthreads();

    // per-lane register preload: Wd as half2 x4, Wv as float x8 (e = lane*8..+7)
    int e0 = lane * 8;
    __half2 wdh[4];
    float wvr[8];
    #pragma unroll
    for (int j = 0; j < 4; j++)
        wdh[j] = __floats2half2_rn(s_wdf[e0 + 2 * j], s_wdf[e0 + 2 * j + 1]);
    #pragma unroll
    for (int j = 0; j < 8; j++) wvr[j] = Wvd[e0 + j];

    const __half* ue = g_Ueh + (size_t)b * T * ENC;
    float bv = bvd[0];

    // scores[t] = sum_e tanh(Wd[e]+Ue[t,e]) * Wv[e] + bv
    #pragma unroll 4
    for (int t = warp; t < T; t += 8) {
        float4 raw = *(const float4*)(ue + t * 256 + e0);
        const __half2* hp = (const __half2*)&raw;
        float acc = 0.f;
        #pragma unroll
        for (int j = 0; j < 4; j++) {
            __half2 th = fast_tanh2(__hadd2(wdh[j], hp[j]));
            float2 f = __half22float2(th);
            acc = fmaf(f.x, wvr[2 * j],     acc);
            acc = fmaf(f.y, wvr[2 * j + 1], acc);
        }
        #pragma unroll
        for (int o = 16; o; o >>= 1) acc += __shfl_xor_sync(0xffffffffu, acc, o);
        if (lane == 0) s_sc[t] = acc + bv;
    }
    __syncthreads();

    // softmax (no max pass: |score| <= ~8, exp safe in fp32)
    float ev = (tid < T) ? __expf(s_sc[tid]) : 0.f;
    if (tid < T) s_sc[tid] = ev;
    float sum = ev;
    #pragma unroll
    for (int o = 16; o; o >>= 1) sum += __shfl_xor_sync(0xffffffffu, sum, o);
    if (lane == 0) s_part[warp] = sum;
    __syncthreads();
    if (tid == 0) {
        float ss = 0.f;
        #pragma unroll
        for (int i = 0; i < 8; i++) ss += s_part[i];
        s_bcast = ss;
    }
    __syncthreads();
    float inv = 1.f / s_bcast;

    // context: thread = (e-chunk of 8, t-group of 8); 16B loads
    int tg = tid >> 5;
    const __half* xb = g_Xh + (size_t)b * T * ENC;
    float acc[8] = {};
    #pragma unroll 4
    for (int t = tg; t < T; t += 8) {
        float beta = s_sc[t];
        float4 raw = *(const float4*)(xb + t * 256 + e0);
        const __half2* hp = (const __half2*)&raw;
        #pragma unroll
        for (int j = 0; j < 4; j++) {
            float2 f = __half22float2(hp[j]);
            acc[2 * j]     = fmaf(beta, f.x, acc[2 * j]);
            acc[2 * j + 1] = fmaf(beta, f.y, acc[2 * j + 1]);
        }
    }
    #pragma unroll
    for (int j = 0; j < 8; j++) s_red[tg][e0 + j] = acc[j];
    __syncthreads();
    float cv = 0.f;
    #pragma unroll
    for (int g = 0; g < 8; g++) cv += s_red[g][tid];
    cv *= inv;
    g_ctx[b * 256 + tid] = cv;

    // y_tilde reduce -> broadcast
    float yv = cv * Ww[tid];
    #pragma unroll
    for (int o = 16; o; o >>= 1) yv += __shfl_xor_sync(0xffffffffu, yv, o);
    if (lane == 0) s_part[warp] = yv;
    __syncthreads();
    if (tid == 0) {
        float ss = 0.f;
        #pragma unroll
        for (int i = 0; i < 8; i++) ss += s_part[i];
        s_bcast = ss + yhist[b * T + step] * Ww[256] + bw[0];
    }
    __syncthreads();
    float yt = s_bcast;

    // ---- LSTM cell for row b, d = tid ----
    const float* gb = g_gates + (size_t)b * 1024;
    float gi = gb[tid]       + yt * Wih[tid];
    float gf = gb[256 + tid] + yt * Wih[256 + tid];
    float gg = gb[512 + tid] + yt * Wih[512 + tid];
    float go = gb[768 + tid] + yt * Wih[768 + tid];
    float ig = 1.f / (1.f + expf(-gi));
    float fg = 1.f / (1.f + expf(-gf));
    float gt = tanhf(gg);
    float og = 1.f / (1.f + expf(-go));
    int nxt = cur ^ 1;
    int idx = b * 256 + tid;
    float cn = fg * g_c[cur][idx] + ig * gt;
    g_c[nxt][idx] = cn;
    g_h[nxt][idx] = og * tanhf(cn);
}

// ---------------- final projection -------------------------------------------
__global__ __launch_bounds__(256) void k_final(
    const float* __restrict__ Wfc, const float* __restrict__ bfc,
    float* __restrict__ out, int fin)
{
    int b = blockIdx.x, tid = threadIdx.x, lane = tid & 31, warp = tid >> 5;
    __shared__ float s_part[8];
    float v = g_h[fin][b * 256 + tid] * Wfc[tid]
            + g_ctx[b * 256 + tid] * Wfc[256 + tid];
    #pragma unroll
    for (int o = 16; o; o >>= 1) v += __shfl_xor_sync(0xffffffffu, v, o);
    if (lane == 0) s_part[warp] = v;
    __syncthreads();
    if (tid == 0) {
        float ss = 0.f;
        #pragma unroll
        for (int i = 0; i < 8; i++) ss += s_part[i];
        out[b] = ss + bfc[0];
    }
}

// ---------------- host -------------------------------------------------------
extern "C" void kernel_launch(void* const* d_in, const int* in_sizes, int n_in,
                              void* d_out, int out_size)
{
    const float* X     = (const float*)d_in[0];
    const float* yhist = (const float*)d_in[1];
    const float* W_vd  = (const float*)d_in[2];
    const float* b_vd  = (const float*)d_in[3];
    const float* W_dhs = (const float*)d_in[4];
    const float* b_dhs = (const float*)d_in[5];
    const float* W_Ud  = (const float*)d_in[6];
    const float* b_Ud  = (const float*)d_in[7];
    const float* W_w   = (const float*)d_in[8];
    const float* b_w   = (const float*)d_in[9];
    const float* W_ih  = (const float*)d_in[10];
    const float* W_hh  = (const float*)d_in[11];
    const float* b_ih  = (const float*)d_in[12];
    const float* b_hh  = (const float*)d_in[13];
    const float* W_fc  = (const float*)d_in[14];
    const float* b_fc  = (const float*)d_in[15];
    float* out = (float*)d_out;

    k_zero_state<<<(BATCH * DEC) / 256, 256>>>();
    {
        dim3 grid(ENC / 64, (BATCH * T) / 128);
        k_gemm_ue<<<grid, 256>>>(X, W_Ud, b_Ud);
    }

    for (int s = 0; s < T; s++) {
        int cur = s & 1;
        k_wd_gates<<<512, 256>>>(W_dhs, W_hh, b_ih, b_hh, cur);
        k_attn_cell<<<BATCH, 256>>>(W_vd, b_vd, b_dhs, W_w, b_w, yhist, W_ih, s, cur);
    }

    k_final<<<BATCH, 256>>>(W_fc, b_fc, out, T & 1);
}

// round 10
// speedup vs baseline: 2.8813x; 1.2209x over previous
#include <cuda_runtime.h>
#include <cuda_fp16.h>
#include <math.h>

#define BATCH 1024
#define T     127
#define ENC   256
#define DEC   256

// ---------------- scratch (device globals) ----------------------------------
__device__ __half g_Ueh[(size_t)BATCH * T * ENC];   // 66.6 MB
__device__ __half g_Xh[(size_t)BATCH * T * ENC];    // 66.6 MB
__device__ float  g_h[2][BATCH * DEC];
__device__ float  g_c[2][BATCH * DEC];
__device__ float  g_WdP[2][BATCH * ENC];            // split-K partials
__device__ float  g_gates[(size_t)BATCH * 4 * DEC];
__device__ float  g_ctx[BATCH * ENC];

// fast f16x2 tanh: cuda_fp16.hpp intrinsic (tanh.approx.f16x2)
__device__ __forceinline__ __half2 fast_tanh2(__half2 x) {
    return h2tanh_approx(x);
}

// ---------------- init ------------------------------------------------------
__global__ void k_zero_state() {
    int i = blockIdx.x * 256 + threadIdx.x;
    g_h[0][i] = 0.f;
    g_c[0][i] = 0.f;
}

// ---------------- Ue GEMM (+ fused X->half convert on n-tile 0) --------------
__global__ __launch_bounds__(256) void k_gemm_ue(
    const float* __restrict__ X, const float* __restrict__ W,
    const float* __restrict__ bias)
{
    __shared__ float sA[16][132];
    __shared__ float sB[16][68];
    int tid = threadIdx.x;
    int m0 = blockIdx.y * 128;
    int n0 = blockIdx.x * 64;
    int tx = tid & 15, ty = tid >> 4;
    bool cvt = (blockIdx.x == 0);
    float acc[8][4] = {};

    for (int k0 = 0; k0 < 256; k0 += 16) {
        #pragma unroll
        for (int i = 0; i < 2; i++) {
            int lin = tid + i * 256;
            int r = lin >> 2, f4 = lin & 3;
            size_t off = (size_t)(m0 + r) * 256 + k0 + f4 * 4;
            float4 v = *(const float4*)(X + off);
            sA[f4 * 4 + 0][r] = v.x; sA[f4 * 4 + 1][r] = v.y;
            sA[f4 * 4 + 2][r] = v.z; sA[f4 * 4 + 3][r] = v.w;
            if (cvt) {
                __half2* dst = (__half2*)(g_Xh + off);
                dst[0] = __floats2half2_rn(v.x, v.y);
                dst[1] = __floats2half2_rn(v.z, v.w);
            }
        }
        {
            int r = tid >> 2, f4 = tid & 3;
            float4 v = *(const float4*)(W + (size_t)(n0 + r) * 256 + k0 + f4 * 4);
            sB[f4 * 4 + 0][r] = v.x; sB[f4 * 4 + 1][r] = v.y;
            sB[f4 * 4 + 2][r] = v.z; sB[f4 * 4 + 3][r] = v.w;
        }
        __syncthreads();
        #pragma unroll
        for (int k = 0; k < 16; k++) {
            float a[8];
            #pragma unroll
            for (int i = 0; i < 8; i++) a[i] = sA[k][ty * 8 + i];
            float4 bv = *(const float4*)&sB[k][tx * 4];
            #pragma unroll
            for (int i = 0; i < 8; i++) {
                acc[i][0] = fmaf(a[i], bv.x, acc[i][0]);
                acc[i][1] = fmaf(a[i], bv.y, acc[i][1]);
                acc[i][2] = fmaf(a[i], bv.z, acc[i][2]);
                acc[i][3] = fmaf(a[i], bv.w, acc[i][3]);
            }
        }
        __syncthreads();
    }
    float b0 = bias[n0 + tx * 4], b1 = bias[n0 + tx * 4 + 1];
    float b2 = bias[n0 + tx * 4 + 2], b3 = bias[n0 + tx * 4 + 3];
    #pragma unroll
    for (int i = 0; i < 8; i++) {
        size_t m = m0 + ty * 8 + i;
        __half2* dst = (__half2*)(g_Ueh + m * 256 + n0 + tx * 4);
        dst[0] = __floats2half2_rn(acc[i][0] + b0, acc[i][1] + b1);
        dst[1] = __floats2half2_rn(acc[i][2] + b2, acc[i][3] + b3);
    }
}

// ---------------- unified Wd + gates GEMM (all 64x64 tiles) ------------------
// blocks [0,128): Wd partials: z = bid>>6, m-tile = (bid>>2)&15, n-tile = bid&3.
// blocks [128,384): gates: m-tile = (bid-128)>>4, n-tile = (bid-128)&15.
__global__ __launch_bounds__(256) void k_wd_gates(
    const float* __restrict__ Wdhs,
    const float* __restrict__ Whh, const float* __restrict__ bih,
    const float* __restrict__ bhh, int cur)
{
    __shared__ float sA[2][16][68];
    __shared__ float sB[2][16][68];
    int tid = threadIdx.x;
    int tx = tid & 15, ty = tid >> 4;
    int r = tid >> 2, f4 = tid & 3;

    const float* A;
    const float* W;
    int ldw;
    float* out;
    int ldo;
    const float* bias1;
    const float* bias2;
    int m0, n0;

    int bid = blockIdx.x;
    if (bid < 128) {
        int z = bid >> 6;
        int rem = bid & 63;
        m0 = ((rem >> 2) & 15) * 64;
        n0 = (rem & 3) * 64;
        A = z ? g_c[cur] : g_h[cur];
        W = Wdhs + z * 256;   ldw = 512;
        out = g_WdP[z];       ldo = 256;
        bias1 = 0; bias2 = 0;
    } else {
        int rem = bid - 128;
        m0 = (rem >> 4) * 64;
        n0 = (rem & 15) * 64;
        A = g_h[cur];
        W = Whh;              ldw = 256;
        out = g_gates;        ldo = 1024;
        bias1 = bih; bias2 = bhh;
    }

    float acc[4][4] = {};
    float4 ra, rb;

    ra = *(const float4*)(A + (size_t)(m0 + r) * 256 + f4 * 4);
    rb = *(const float4*)(W + (size_t)(n0 + r) * ldw + f4 * 4);
    sA[0][f4 * 4 + 0][r] = ra.x; sA[0][f4 * 4 + 1][r] = ra.y;
    sA[0][f4 * 4 + 2][r] = ra.z; sA[0][f4 * 4 + 3][r] = ra.w;
    sB[0][f4 * 4 + 0][r] = rb.x; sB[0][f4 * 4 + 1][r] = rb.y;
    sB[0][f4 * 4 + 2][r] = rb.z; sB[0][f4 * 4 + 3][r] = rb.w;
    __syncthreads();

    #pragma unroll
    for (int it = 0; it < 16; it++) {
        int cb = it & 1;
        if (it < 15) {
            int k0 = (it + 1) * 16;
            ra = *(const float4*)(A + (size_t)(m0 + r) * 256 + k0 + f4 * 4);
            rb = *(const float4*)(W + (size_t)(n0 + r) * ldw + k0 + f4 * 4);
        }
        #pragma unroll
        for (int k = 0; k < 16; k++) {
            float4 a = *(const float4*)&sA[cb][k][ty * 4];
            float am[4] = {a.x, a.y, a.z, a.w};
            float4 bv = *(const float4*)&sB[cb][k][tx * 4];
            #pragma unroll
            for (int i = 0; i < 4; i++) {
                acc[i][0] = fmaf(am[i], bv.x, acc[i][0]);
                acc[i][1] = fmaf(am[i], bv.y, acc[i][1]);
                acc[i][2] = fmaf(am[i], bv.z, acc[i][2]);
                acc[i][3] = fmaf(am[i], bv.w, acc[i][3]);
            }
        }
        if (it < 15) {
            int nb = cb ^ 1;
            sA[nb][f4 * 4 + 0][r] = ra.x; sA[nb][f4 * 4 + 1][r] = ra.y;
            sA[nb][f4 * 4 + 2][r] = ra.z; sA[nb][f4 * 4 + 3][r] = ra.w;
            sB[nb][f4 * 4 + 0][r] = rb.x; sB[nb][f4 * 4 + 1][r] = rb.y;
            sB[nb][f4 * 4 + 2][r] = rb.z; sB[nb][f4 * 4 + 3][r] = rb.w;
        }
        __syncthreads();
    }
    #pragma unroll
    for (int i = 0; i < 4; i++) {
        int m = m0 + ty * 4 + i;
        #pragma unroll
        for (int j = 0; j < 4; j++) {
            int n = n0 + tx * 4 + j;
            float v = acc[i][j];
            if (bias1) v += bias1[n] + bias2[n];
            out[(size_t)m * ldo + n] = v;
        }
    }
}

// ---------------- fused one-pass attention + LSTM cell -----------------------
// block b: single pass over Ue and X rows — score, exp, weighted accumulate.
__global__ __launch_bounds__(256) void k_attn_cell(
    const float* __restrict__ Wvd, const float* __restrict__ bvd,
    const float* __restrict__ bdhs,
    const float* __restrict__ Ww,  const float* __restrict__ bw,
    const float* __restrict__ yhist,
    const float* __restrict__ Wih, int step, int cur)
{
    int b = blockIdx.x;
    int tid = threadIdx.x, lane = tid & 31, warp = tid >> 5;
    __shared__ float s_wdf[256];
    __shared__ float s_red[8][264];
    __shared__ float s_part[8];
    __shared__ float s_bcast;

    s_wdf[tid] = g_WdP[0][b * 256 + tid] + g_WdP[1][b * 256 + tid] + bdhs[tid];
    __syncthreads();

    int e0 = lane * 8;
    __half2 wdh[4];
    float wvr[8];
    #pragma unroll
    for (int j = 0; j < 4; j++)
        wdh[j] = __floats2half2_rn(s_wdf[e0 + 2 * j], s_wdf[e0 + 2 * j + 1]);
    #pragma unroll
    for (int j = 0; j < 8; j++) wvr[j] = Wvd[e0 + j];

    const __half* ue = g_Ueh + (size_t)b * T * ENC;
    const __half* xb = g_Xh + (size_t)b * T * ENC;
    float bv = bvd[0];

    // one pass: score -> exp -> weighted context accumulate
    float ctx[8] = {};
    float sumexp = 0.f;
    #pragma unroll 4
    for (int t = warp; t < T; t += 8) {
        float4 uraw = *(const float4*)(ue + t * 256 + e0);
        float4 xraw = *(const float4*)(xb + t * 256 + e0);
        const __half2* up = (const __half2*)&uraw;
        float acc = 0.f;
        #pragma unroll
        for (int j = 0; j < 4; j++) {
            __half2 th = fast_tanh2(__hadd2(wdh[j], up[j]));
            float2 f = __half22float2(th);
            acc = fmaf(f.x, wvr[2 * j],     acc);
            acc = fmaf(f.y, wvr[2 * j + 1], acc);
        }
        #pragma unroll
        for (int o = 16; o; o >>= 1) acc += __shfl_xor_sync(0xffffffffu, acc, o);
        float ew = __expf(acc + bv);     // no max pass: |score| bounded
        sumexp += ew;
        const __half2* xp = (const __half2*)&xraw;
        #pragma unroll
        for (int j = 0; j < 4; j++) {
            float2 f = __half22float2(xp[j]);
            ctx[2 * j]     = fmaf(ew, f.x, ctx[2 * j]);
            ctx[2 * j + 1] = fmaf(ew, f.y, ctx[2 * j + 1]);
        }
    }
    #pragma unroll
    for (int j = 0; j < 8; j++) s_red[warp][e0 + j] = ctx[j];
    if (lane == 0) s_part[warp] = sumexp;
    __syncthreads();
    if (tid == 0) {
        float ss = 0.f;
        #pragma unroll
        for (int i = 0; i < 8; i++) ss += s_part[i];
        s_bcast = ss;
    }
    __syncthreads();
    float inv = 1.f / s_bcast;

    float cv = 0.f;
    #pragma unroll
    for (int g = 0; g < 8; g++) cv += s_red[g][tid];
    cv *= inv;
    g_ctx[b * 256 + tid] = cv;

    // y_tilde reduce -> broadcast
    float yv = cv * Ww[tid];
    #pragma unroll
    for (int o = 16; o; o >>= 1) yv += __shfl_xor_sync(0xffffffffu, yv, o);
    if (lane == 0) s_part[warp] = yv;
    __syncthreads();
    if (tid == 0) {
        float ss = 0.f;
        #pragma unroll
        for (int i = 0; i < 8; i++) ss += s_part[i];
        s_bcast = ss + yhist[b * T + step] * Ww[256] + bw[0];
    }
    __syncthreads();
    float yt = s_bcast;

    // LSTM cell for row b, d = tid
    const float* gb = g_gates + (size_t)b * 1024;
    float gi = gb[tid]       + yt * Wih[tid];
    float gf = gb[256 + tid] + yt * Wih[256 + tid];
    float gg = gb[512 + tid] + yt * Wih[512 + tid];
    float go = gb[768 + tid] + yt * Wih[768 + tid];
    float ig = 1.f / (1.f + expf(-gi));
    float fg = 1.f / (1.f + expf(-gf));
    float gt = tanhf(gg);
    float og = 1.f / (1.f + expf(-go));
    int nxt = cur ^ 1;
    int idx = b * 256 + tid;
    float cn = fg * g_c[cur][idx] + ig * gt;
    g_c[nxt][idx] = cn;
    g_h[nxt][idx] = og * tanhf(cn);
}

// ---------------- final projection -------------------------------------------
__global__ __launch_bounds__(256) void k_final(
    const float* __restrict__ Wfc, const float* __restrict__ bfc,
    float* __restrict__ out, int fin)
{
    int b = blockIdx.x, tid = threadIdx.x, lane = tid & 31, warp = tid >> 5;
    __shared__ float s_part[8];
    float v = g_h[fin][b * 256 + tid] * Wfc[tid]
            + g_ctx[b * 256 + tid] * Wfc[256 + tid];
    #pragma unroll
    for (int o = 16; o; o >>= 1) v += __shfl_xor_sync(0xffffffffu, v, o);
    if (lane == 0) s_part[warp] = v;
    __syncthreads();
    if (tid == 0) {
        float ss = 0.f;
        #pragma unroll
        for (int i = 0; i < 8; i++) ss += s_part[i];
        out[b] = ss + bfc[0];
    }
}

// ---------------- host -------------------------------------------------------
extern "C" void kernel_launch(void* const* d_in, const int* in_sizes, int n_in,
                              void* d_out, int out_size)
{
    const float* X     = (const float*)d_in[0];
    const float* yhist = (const float*)d_in[1];
    const float* W_vd  = (const float*)d_in[2];
    const float* b_vd  = (const float*)d_in[3];
    const float* W_dhs = (const float*)d_in[4];
    const float* b_dhs = (const float*)d_in[5];
    const float* W_Ud  = (const float*)d_in[6];
    const float* b_Ud  = (const float*)d_in[7];
    const float* W_w   = (const float*)d_in[8];
    const float* b_w   = (const float*)d_in[9];
    const float* W_ih  = (const float*)d_in[10];
    const float* W_hh  = (const float*)d_in[11];
    const float* b_ih  = (const float*)d_in[12];
    const float* b_hh  = (const float*)d_in[13];
    const float* W_fc  = (const float*)d_in[14];
    const float* b_fc  = (const float*)d_in[15];
    float* out = (float*)d_out;

    k_zero_state<<<(BATCH * DEC) / 256, 256>>>();
    {
        dim3 grid(ENC / 64, (BATCH * T) / 128);
        k_gemm_ue<<<grid, 256>>>(X, W_Ud, b_Ud);
    }

    for (int s = 0; s < T; s++) {
        int cur = s & 1;
        k_wd_gates<<<384, 256>>>(W_dhs, W_hh, b_ih, b_hh, cur);
        k_attn_cell<<<BATCH, 256>>>(W_vd, b_vd, b_dhs, W_w, b_w, yhist, W_ih, s, cur);
    }

    k_final<<<BATCH, 256>>>(W_fc, b_fc, out, T & 1);
}

// round 11
// speedup vs baseline: 2.9813x; 1.0347x over previous
#include <cuda_runtime.h>
#include <cuda_fp16.h>
#include <mma.h>
#include <math.h>

using namespace nvcuda;

#define BATCH 1024
#define T     127
#define ENC   256
#define DEC   256

// ---------------- scratch (device globals) ----------------------------------
__device__ __half g_Ueh[(size_t)BATCH * T * ENC];   // 66.6 MB
__device__ __half g_Xh[(size_t)BATCH * T * ENC];    // 66.6 MB
__device__ __half g_Wh[ENC * ENC];                  // W_Ud fp16
__device__ float  g_h[2][BATCH * DEC];
__device__ float  g_c[2][BATCH * DEC];
__device__ float  g_WdP[2][BATCH * ENC];            // split-K partials
__device__ float  g_gates[(size_t)BATCH * 4 * DEC];
__device__ float  g_ctx[BATCH * ENC];

__device__ __forceinline__ __half2 fast_tanh2(__half2 x) {
    return h2tanh_approx(x);
}

// ---------------- init ------------------------------------------------------
__global__ void k_zero_state() {
    int i = blockIdx.x * 256 + threadIdx.x;
    g_h[0][i] = 0.f;
    g_c[0][i] = 0.f;
}

// ---------------- converts --------------------------------------------------
__global__ __launch_bounds__(256) void k_convert_x(const float* __restrict__ X) {
    size_t i = ((size_t)blockIdx.x * 256 + threadIdx.x) * 4;
    float4 v = *(const float4*)(X + i);
    *(__half2*)(g_Xh + i)     = __floats2half2_rn(v.x, v.y);
    *(__half2*)(g_Xh + i + 2) = __floats2half2_rn(v.z, v.w);
}
__global__ __launch_bounds__(256) void k_convert_w(const float* __restrict__ W) {
    int i = blockIdx.x * 256 + threadIdx.x;
    g_Wh[i] = __float2half(W[i]);
}

// ---------------- Ue GEMM via fp16 wmma (fp32 accum) --------------------------
// tile 64m x 64n, K=256 in 2 chunks of 128. 8 warps: 4 m-warps x 2 n-warps,
// each warp 16x32 (2 fragments). Output: half with bias.
__global__ __launch_bounds__(256) void k_ue_wmma(const float* __restrict__ bias)
{
    __shared__ __half sA[64][136];
    __shared__ __half sB[64][136];
    int tid = threadIdx.x;
    int warp = tid >> 5;
    int wm = warp >> 1, wn = warp & 1;
    size_t m0 = (size_t)blockIdx.y * 64;
    int n0 = blockIdx.x * 64;

    wmma::fragment<wmma::accumulator, 16, 16, 16, float> cfrag[2];
    wmma::fill_fragment(cfrag[0], 0.f);
    wmma::fill_fragment(cfrag[1], 0.f);

    for (int kc = 0; kc < 256; kc += 128) {
        #pragma unroll
        for (int i = 0; i < 4; i++) {
            int lin = tid + i * 256;
            int r = lin >> 4, cb = lin & 15;
            *(float4*)&sA[r][cb * 8] =
                *(const float4*)(g_Xh + (m0 + r) * 256 + kc + cb * 8);
        }
        #pragma unroll
        for (int i = 0; i < 4; i++) {
            int lin = tid + i * 256;
            int r = lin >> 4, cb = lin & 15;
            *(float4*)&sB[r][cb * 8] =
                *(const float4*)(g_Wh + (size_t)(n0 + r) * 256 + kc + cb * 8);
        }
        __syncthreads();
        #pragma unroll
        for (int k = 0; k < 128; k += 16) {
            wmma::fragment<wmma::matrix_a, 16, 16, 16, __half, wmma::row_major> afrag;
            wmma::load_matrix_sync(afrag, &sA[wm * 16][k], 136);
            #pragma unroll
            for (int j = 0; j < 2; j++) {
                wmma::fragment<wmma::matrix_b, 16, 16, 16, __half, wmma::col_major> bfrag;
                wmma::load_matrix_sync(bfrag, &sB[wn * 32 + j * 16][k], 136);
                wmma::mma_sync(cfrag[j], afrag, bfrag, cfrag[j]);
            }
        }
        __syncthreads();
    }

    // bounce fp32 results through smem (reuse sA: 64x68 floats = 17408 B)
    float* cs = (float*)&sA[0][0];
    wmma::store_matrix_sync(cs + (wm * 16) * 68 + wn * 32,      cfrag[0], 68, wmma::mem_row_major);
    wmma::store_matrix_sync(cs + (wm * 16) * 68 + wn * 32 + 16, cfrag[1], 68, wmma::mem_row_major);
    __syncthreads();

    int r = tid >> 2, c0 = (tid & 3) * 16;
    __half2* dst = (__half2*)(g_Ueh + (m0 + r) * 256 + n0 + c0);
    #pragma unroll
    for (int j = 0; j < 16; j += 2) {
        float v0 = cs[r * 68 + c0 + j]     + bias[n0 + c0 + j];
        float v1 = cs[r * 68 + c0 + j + 1] + bias[n0 + c0 + j + 1];
        dst[j >> 1] = __floats2half2_rn(v0, v1);
    }
}

// ---------------- unified Wd + gates GEMM (all 64x64 tiles) ------------------
__global__ __launch_bounds__(256) void k_wd_gates(
    const float* __restrict__ Wdhs,
    const float* __restrict__ Whh, const float* __restrict__ bih,
    const float* __restrict__ bhh, int cur)
{
    __shared__ float sA[2][16][68];
    __shared__ float sB[2][16][68];
    int tid = threadIdx.x;
    int tx = tid & 15, ty = tid >> 4;
    int r = tid >> 2, f4 = tid & 3;

    const float* A;
    const float* W;
    int ldw;
    float* out;
    int ldo;
    const float* bias1;
    const float* bias2;
    int m0, n0;

    int bid = blockIdx.x;
    if (bid < 128) {
        int z = bid >> 6;
        int rem = bid & 63;
        m0 = ((rem >> 2) & 15) * 64;
        n0 = (rem & 3) * 64;
        A = z ? g_c[cur] : g_h[cur];
        W = Wdhs + z * 256;   ldw = 512;
        out = g_WdP[z];       ldo = 256;
        bias1 = 0; bias2 = 0;
    } else {
        int rem = bid - 128;
        m0 = (rem >> 4) * 64;
        n0 = (rem & 15) * 64;
        A = g_h[cur];
        W = Whh;              ldw = 256;
        out = g_gates;        ldo = 1024;
        bias1 = bih; bias2 = bhh;
    }

    float acc[4][4] = {};
    float4 ra, rb;

    ra = *(const float4*)(A + (size_t)(m0 + r) * 256 + f4 * 4);
    rb = *(const float4*)(W + (size_t)(n0 + r) * ldw + f4 * 4);
    sA[0][f4 * 4 + 0][r] = ra.x; sA[0][f4 * 4 + 1][r] = ra.y;
    sA[0][f4 * 4 + 2][r] = ra.z; sA[0][f4 * 4 + 3][r] = ra.w;
    sB[0][f4 * 4 + 0][r] = rb.x; sB[0][f4 * 4 + 1][r] = rb.y;
    sB[0][f4 * 4 + 2][r] = rb.z; sB[0][f4 * 4 + 3][r] = rb.w;
    __syncthreads();

    #pragma unroll
    for (int it = 0; it < 16; it++) {
        int cb = it & 1;
        if (it < 15) {
            int k0 = (it + 1) * 16;
            ra = *(const float4*)(A + (size_t)(m0 + r) * 256 + k0 + f4 * 4);
            rb = *(const float4*)(W + (size_t)(n0 + r) * ldw + k0 + f4 * 4);
        }
        #pragma unroll
        for (int k = 0; k < 16; k++) {
            float4 a = *(const float4*)&sA[cb][k][ty * 4];
            float am[4] = {a.x, a.y, a.z, a.w};
            float4 bv = *(const float4*)&sB[cb][k][tx * 4];
            #pragma unroll
            for (int i = 0; i < 4; i++) {
                acc[i][0] = fmaf(am[i], bv.x, acc[i][0]);
                acc[i][1] = fmaf(am[i], bv.y, acc[i][1]);
                acc[i][2] = fmaf(am[i], bv.z, acc[i][2]);
                acc[i][3] = fmaf(am[i], bv.w, acc[i][3]);
            }
        }
        if (it < 15) {
            int nb = cb ^ 1;
            sA[nb][f4 * 4 + 0][r] = ra.x; sA[nb][f4 * 4 + 1][r] = ra.y;
            sA[nb][f4 * 4 + 2][r] = ra.z; sA[nb][f4 * 4 + 3][r] = ra.w;
            sB[nb][f4 * 4 + 0][r] = rb.x; sB[nb][f4 * 4 + 1][r] = rb.y;
            sB[nb][f4 * 4 + 2][r] = rb.z; sB[nb][f4 * 4 + 3][r] = rb.w;
        }
        __syncthreads();
    }
    #pragma unroll
    for (int i = 0; i < 4; i++) {
        int m = m0 + ty * 4 + i;
        #pragma unroll
        for (int j = 0; j < 4; j++) {
            int n = n0 + tx * 4 + j;
            float v = acc[i][j];
            if (bias1) v += bias1[n] + bias2[n];
            out[(size_t)m * ldo + n] = v;
        }
    }
}

// ---------------- fused one-pass attention + LSTM cell -----------------------
// 4-way grouped t-processing: interleaved butterfly chains, X loads hide them.
__global__ __launch_bounds__(256) void k_attn_cell(
    const float* __restrict__ Wvd, const float* __restrict__ bvd,
    const float* __restrict__ bdhs,
    const float* __restrict__ Ww,  const float* __restrict__ bw,
    const float* __restrict__ yhist,
    const float* __restrict__ Wih, int step, int cur)
{
    int b = blockIdx.x;
    int tid = threadIdx.x, lane = tid & 31, warp = tid >> 5;
    __shared__ float s_wdf[256];
    __shared__ float s_red[8][264];
    __shared__ float s_part[8];
    __shared__ float s_bcast;

    s_wdf[tid] = g_WdP[0][b * 256 + tid] + g_WdP[1][b * 256 + tid] + bdhs[tid];
    __syncthreads();

    int e0 = lane * 8;
    __half2 wdh[4];
    float wvr[8];
    #pragma unroll
    for (int j = 0; j < 4; j++)
        wdh[j] = __floats2half2_rn(s_wdf[e0 + 2 * j], s_wdf[e0 + 2 * j + 1]);
    #pragma unroll
    for (int j = 0; j < 8; j++) wvr[j] = Wvd[e0 + j];

    const __half* ue = g_Ueh + (size_t)b * T * ENC;
    const __half* xb = g_Xh + (size_t)b * T * ENC;
    float bv = bvd[0];

    float ctx[8] = {};
    float sumexp = 0.f;

    #pragma unroll
    for (int g = 0; g < 4; g++) {
        float acc[4];
        float4 xraw[4];
        {
            float4 uraw[4];
            #pragma unroll
            for (int u = 0; u < 4; u++) {
                int t = warp + (g * 4 + u) * 8;
                int te = t < T ? t : 0;
                uraw[u] = *(const float4*)(ue + te * 256 + e0);
            }
            // prefetch X rows (independent of scores) — hides butterfly latency
            #pragma unroll
            for (int u = 0; u < 4; u++) {
                int t = warp + (g * 4 + u) * 8;
                int te = t < T ? t : 0;
                xraw[u] = *(const float4*)(xb + te * 256 + e0);
            }
            #pragma unroll
            for (int u = 0; u < 4; u++) {
                const __half2* up = (const __half2*)&uraw[u];
                float a = 0.f;
                #pragma unroll
                for (int j = 0; j < 4; j++) {
                    __half2 th = fast_tanh2(__hadd2(wdh[j], up[j]));
                    float2 f = __half22float2(th);
                    a = fmaf(f.x, wvr[2 * j],     a);
                    a = fmaf(f.y, wvr[2 * j + 1], a);
                }
                acc[u] = a;
            }
        }
        // 4 interleaved butterfly chains — latency of ~one chain
        #pragma unroll
        for (int o = 16; o; o >>= 1) {
            #pragma unroll
            for (int u = 0; u < 4; u++)
                acc[u] += __shfl_xor_sync(0xffffffffu, acc[u], o);
        }
        float ew[4];
        #pragma unroll
        for (int u = 0; u < 4; u++) {
            int t = warp + (g * 4 + u) * 8;
            ew[u] = (t < T) ? __expf(acc[u] + bv) : 0.f;
            sumexp += ew[u];
        }
        #pragma unroll
        for (int u = 0; u < 4; u++) {
            const __half2* xp = (const __half2*)&xraw[u];
            #pragma unroll
            for (int j = 0; j < 4; j++) {
                float2 f = __half22float2(xp[j]);
                ctx[2 * j]     = fmaf(ew[u], f.x, ctx[2 * j]);
                ctx[2 * j + 1] = fmaf(ew[u], f.y, ctx[2 * j + 1]);
            }
        }
    }
    #pragma unroll
    for (int j = 0; j < 8; j++) s_red[warp][e0 + j] = ctx[j];
    if (lane == 0) s_part[warp] = sumexp;
    __syncthreads();
    if (tid == 0) {
        float ss = 0.f;
        #pragma unroll
        for (int i = 0; i < 8; i++) ss += s_part[i];
        s_bcast = ss;
    }
    __syncthreads();
    float inv = 1.f / s_bcast;

    float cv = 0.f;
    #pragma unroll
    for (int g = 0; g < 8; g++) cv += s_red[g][tid];
    cv *= inv;
    g_ctx[b * 256 + tid] = cv;

    // y_tilde reduce -> broadcast
    float yv = cv * Ww[tid];
    #pragma unroll
    for (int o = 16; o; o >>= 1) yv += __shfl_xor_sync(0xffffffffu, yv, o);
    if (lane == 0) s_part[warp] = yv;
    __syncthreads();
    if (tid == 0) {
        float ss = 0.f;
        #pragma unroll
        for (int i = 0; i < 8; i++) ss += s_part[i];
        s_bcast = ss + yhist[b * T + step] * Ww[256] + bw[0];
    }
    __syncthreads();
    float yt = s_bcast;

    // LSTM cell for row b, d = tid
    const float* gb = g_gates + (size_t)b * 1024;
    float gi = gb[tid]       + yt * Wih[tid];
    float gf = gb[256 + tid] + yt * Wih[256 + tid];
    float gg = gb[512 + tid] + yt * Wih[512 + tid];
    float go = gb[768 + tid] + yt * Wih[768 + tid];
    float ig = 1.f / (1.f + expf(-gi));
    float fg = 1.f / (1.f + expf(-gf));
    float gt = tanhf(gg);
    float og = 1.f / (1.f + expf(-go));
    int nxt = cur ^ 1;
    int idx = b * 256 + tid;
    float cn = fg * g_c[cur][idx] + ig * gt;
    g_c[nxt][idx] = cn;
    g_h[nxt][idx] = og * tanhf(cn);
}

// ---------------- final projection -------------------------------------------
__global__ __launch_bounds__(256) void k_final(
    const float* __restrict__ Wfc, const float* __restrict__ bfc,
    float* __restrict__ out, int fin)
{
    int b = blockIdx.x, tid = threadIdx.x, lane = tid & 31, warp = tid >> 5;
    __shared__ float s_part[8];
    float v = g_h[fin][b * 256 + tid] * Wfc[tid]
            + g_ctx[b * 256 + tid] * Wfc[256 + tid];
    #pragma unroll
    for (int o = 16; o; o >>= 1) v += __shfl_xor_sync(0xffffffffu, v, o);
    if (lane == 0) s_part[warp] = v;
    __syncthreads();
    if (tid == 0) {
        float ss = 0.f;
        #pragma unroll
        for (int i = 0; i < 8; i++) ss += s_part[i];
        out[b] = ss + bfc[0];
    }
}

// ---------------- host -------------------------------------------------------
extern "C" void kernel_launch(void* const* d_in, const int* in_sizes, int n_in,
                              void* d_out, int out_size)
{
    const float* X     = (const float*)d_in[0];
    const float* yhist = (const float*)d_in[1];
    const float* W_vd  = (const float*)d_in[2];
    const float* b_vd  = (const float*)d_in[3];
    const float* W_dhs = (const float*)d_in[4];
    const float* b_dhs = (const float*)d_in[5];
    const float* W_Ud  = (const float*)d_in[6];
    const float* b_Ud  = (const float*)d_in[7];
    const float* W_w   = (const float*)d_in[8];
    const float* b_w   = (const float*)d_in[9];
    const float* W_ih  = (const float*)d_in[10];
    const float* W_hh  = (const float*)d_in[11];
    const float* b_ih  = (const float*)d_in[12];
    const float* b_hh  = (const float*)d_in[13];
    const float* W_fc  = (const float*)d_in[14];
    const float* b_fc  = (const float*)d_in[15];
    float* out = (float*)d_out;

    k_zero_state<<<(BATCH * DEC) / 256, 256>>>();
    k_convert_x<<<((size_t)BATCH * T * ENC) / 4 / 256, 256>>>(X);
    k_convert_w<<<(ENC * ENC) / 256, 256>>>(W_Ud);
    {
        dim3 grid(ENC / 64, (BATCH * T) / 64);
        k_ue_wmma<<<grid, 256>>>(b_Ud);
    }

    for (int s = 0; s < T; s++) {
        int cur = s & 1;
        k_wd_gates<<<384, 256>>>(W_dhs, W_hh, b_ih, b_hh, cur);
        k_attn_cell<<<BATCH, 256>>>(W_vd, b_vd, b_dhs, W_w, b_w, yhist, W_ih, s, cur);
    }

    k_final<<<BATCH, 256>>>(W_fc, b_fc, out, T & 1);
}

// round 12
// speedup vs baseline: 3.7753x; 1.2663x over previous
#include <cuda_runtime.h>
#include <cuda_fp16.h>
#include <mma.h>
#include <math.h>

using namespace nvcuda;

#define BATCH 1024
#define T     127
#define ENC   256
#define DEC   256

// ---------------- scratch (device globals) ----------------------------------
__device__ __half g_Ueh[(size_t)BATCH * T * ENC];   // 66.6 MB
__device__ __half g_Xh[(size_t)BATCH * T * ENC];    // 66.6 MB
__device__ __half g_Wh[ENC * ENC];                  // W_Ud fp16
__device__ __half g_Wdhs_h[ENC * 2 * DEC];          // W_dhs fp16 (256x512)
__device__ __half g_Whh_h[4 * DEC * DEC];           // W_hh fp16 (1024x256)
__device__ float  g_h[2][BATCH * DEC];
__device__ float  g_c[2][BATCH * DEC];
__device__ __half g_hh[BATCH * DEC];                // fp16 copy of current h
__device__ __half g_ch[BATCH * DEC];                // fp16 copy of current c
__device__ float  g_Wd[BATCH * ENC];                // bias-folded Wd
__device__ float  g_gates[(size_t)BATCH * 4 * DEC];
__device__ float  g_ctx[BATCH * ENC];

__device__ __forceinline__ __half2 fast_tanh2(__half2 x) {
    return h2tanh_approx(x);
}

// ---------------- init ------------------------------------------------------
__global__ void k_zero_state() {
    int i = blockIdx.x * 256 + threadIdx.x;
    g_h[0][i] = 0.f;
    g_c[0][i] = 0.f;
    g_hh[i] = __float2half(0.f);
    g_ch[i] = __float2half(0.f);
}

// ---------------- converts --------------------------------------------------
__global__ __launch_bounds__(256) void k_convert_x(const float* __restrict__ X) {
    size_t i = ((size_t)blockIdx.x * 256 + threadIdx.x) * 4;
    float4 v = *(const float4*)(X + i);
    *(__half2*)(g_Xh + i)     = __floats2half2_rn(v.x, v.y);
    *(__half2*)(g_Xh + i + 2) = __floats2half2_rn(v.z, v.w);
}
__global__ __launch_bounds__(256) void k_convert_w(__half* dst, const float* __restrict__ src) {
    int i = blockIdx.x * 256 + threadIdx.x;
    dst[i] = __float2half(src[i]);
}

// ---------------- Ue GEMM via fp16 wmma (fp32 accum) --------------------------
__global__ __launch_bounds__(256) void k_ue_wmma(const float* __restrict__ bias)
{
    __shared__ __half sA[64][136];
    __shared__ __half sB[64][136];
    int tid = threadIdx.x;
    int warp = tid >> 5;
    int wm = warp >> 1, wn = warp & 1;
    size_t m0 = (size_t)blockIdx.y * 64;
    int n0 = blockIdx.x * 64;

    wmma::fragment<wmma::accumulator, 16, 16, 16, float> cfrag[2];
    wmma::fill_fragment(cfrag[0], 0.f);
    wmma::fill_fragment(cfrag[1], 0.f);

    for (int kc = 0; kc < 256; kc += 128) {
        #pragma unroll
        for (int i = 0; i < 4; i++) {
            int lin = tid + i * 256;
            int r = lin >> 4, cb = lin & 15;
            *(float4*)&sA[r][cb * 8] =
                *(const float4*)(g_Xh + (m0 + r) * 256 + kc + cb * 8);
        }
        #pragma unroll
        for (int i = 0; i < 4; i++) {
            int lin = tid + i * 256;
            int r = lin >> 4, cb = lin & 15;
            *(float4*)&sB[r][cb * 8] =
                *(const float4*)(g_Wh + (size_t)(n0 + r) * 256 + kc + cb * 8);
        }
        __syncthreads();
        #pragma unroll
        for (int k = 0; k < 128; k += 16) {
            wmma::fragment<wmma::matrix_a, 16, 16, 16, __half, wmma::row_major> afrag;
            wmma::load_matrix_sync(afrag, &sA[wm * 16][k], 136);
            #pragma unroll
            for (int j = 0; j < 2; j++) {
                wmma::fragment<wmma::matrix_b, 16, 16, 16, __half, wmma::col_major> bfrag;
                wmma::load_matrix_sync(bfrag, &sB[wn * 32 + j * 16][k], 136);
                wmma::mma_sync(cfrag[j], afrag, bfrag, cfrag[j]);
            }
        }
        __syncthreads();
    }

    float* cs = (float*)&sA[0][0];
    wmma::store_matrix_sync(cs + (wm * 16) * 68 + wn * 32,      cfrag[0], 68, wmma::mem_row_major);
    wmma::store_matrix_sync(cs + (wm * 16) * 68 + wn * 32 + 16, cfrag[1], 68, wmma::mem_row_major);
    __syncthreads();

    int r = tid >> 2, c0 = (tid & 3) * 16;
    __half2* dst = (__half2*)(g_Ueh + (m0 + r) * 256 + n0 + c0);
    #pragma unroll
    for (int j = 0; j < 16; j += 2) {
        float v0 = cs[r * 68 + c0 + j]     + bias[n0 + c0 + j];
        float v1 = cs[r * 68 + c0 + j + 1] + bias[n0 + c0 + j + 1];
        dst[j >> 1] = __floats2half2_rn(v0, v1);
    }
}

// ---------------- Wd + gates via fp16 wmma ------------------------------------
// blocks [0,64): Wd tiles (M=1024,N=256,K=512; A = [h|c] fp16, full K per block)
// blocks [64,320): gates tiles (M=1024,N=1024,K=256; A = h fp16)
__global__ __launch_bounds__(256) void k_wd_gates(
    const float* __restrict__ bdhs,
    const float* __restrict__ bih, const float* __restrict__ bhh)
{
    __shared__ union {
        struct { __half A[64][72]; __half B[64][72]; } h;
        float C[64][68];
    } sm;
    int tid = threadIdx.x;
    int warp = tid >> 5;
    int wm = warp >> 1, wn = warp & 1;
    int bid = blockIdx.x;

    int m0, n0, nk, ldw;
    const __half* Wsrc;
    bool is_wd = (bid < 64);
    if (is_wd) {
        m0 = (bid >> 2) * 64;
        n0 = (bid & 3) * 64;
        nk = 8;  ldw = 512;  Wsrc = g_Wdhs_h;
    } else {
        int rem = bid - 64;
        m0 = (rem >> 4) * 64;
        n0 = (rem & 15) * 64;
        nk = 4;  ldw = 256;  Wsrc = g_Whh_h;
    }

    wmma::fragment<wmma::accumulator, 16, 16, 16, float> cfrag[2];
    wmma::fill_fragment(cfrag[0], 0.f);
    wmma::fill_fragment(cfrag[1], 0.f);

    int r8 = tid >> 3, cb8 = tid & 7;   // A/B loads: 64 rows x 8 chunks of 8 halves
    for (int c = 0; c < nk; c++) {
        int kc = c * 64;
        // A chunk: h for k<256, c for k>=256 (wd only reaches k>=256)
        const __half* Asrc = (kc < 256) ? g_hh : g_ch;
        int kof = (kc < 256) ? kc : (kc - 256);
        #pragma unroll
        for (int i = 0; i < 2; i++) {
            int lin = tid + i * 256;
            int r = lin >> 3, cb = lin & 7;
            *(float4*)&sm.h.A[r][cb * 8] =
                *(const float4*)(Asrc + (size_t)(m0 + r) * 256 + kof + cb * 8);
        }
        #pragma unroll
        for (int i = 0; i < 2; i++) {
            int lin = tid + i * 256;
            int r = lin >> 3, cb = lin & 7;
            *(float4*)&sm.h.B[r][cb * 8] =
                *(const float4*)(Wsrc + (size_t)(n0 + r) * ldw + kc + cb * 8);
        }
        __syncthreads();
        #pragma unroll
        for (int k = 0; k < 64; k += 16) {
            wmma::fragment<wmma::matrix_a, 16, 16, 16, __half, wmma::row_major> afrag;
            wmma::load_matrix_sync(afrag, &sm.h.A[wm * 16][k], 72);
            #pragma unroll
            for (int j = 0; j < 2; j++) {
                wmma::fragment<wmma::matrix_b, 16, 16, 16, __half, wmma::col_major> bfrag;
                wmma::load_matrix_sync(bfrag, &sm.h.B[wn * 32 + j * 16][k], 72);
                wmma::mma_sync(cfrag[j], afrag, bfrag, cfrag[j]);
            }
        }
        __syncthreads();
    }

    wmma::store_matrix_sync(&sm.C[wm * 16][wn * 32],      cfrag[0], 68, wmma::mem_row_major);
    wmma::store_matrix_sync(&sm.C[wm * 16][wn * 32 + 16], cfrag[1], 68, wmma::mem_row_major);
    __syncthreads();

    int r = tid >> 2, c0 = (tid & 3) * 16;
    int m = m0 + r;
    if (is_wd) {
        #pragma unroll
        for (int j = 0; j < 16; j++) {
            int n = n0 + c0 + j;
            g_Wd[m * 256 + n] = sm.C[r][c0 + j] + bdhs[n];
        }
    } else {
        #pragma unroll
        for (int j = 0; j < 16; j++) {
            int n = n0 + c0 + j;
            g_gates[(size_t)m * 1024 + n] = sm.C[r][c0 + j] + bih[n] + bhh[n];
        }
    }
}

// ---------------- fused one-pass attention + LSTM cell -----------------------
__global__ __launch_bounds__(256) void k_attn_cell(
    const float* __restrict__ Wvd, const float* __restrict__ bvd,
    const float* __restrict__ Ww,  const float* __restrict__ bw,
    const float* __restrict__ yhist,
    const float* __restrict__ Wih, int step, int cur)
{
    int b = blockIdx.x;
    int tid = threadIdx.x, lane = tid & 31, warp = tid >> 5;
    __shared__ float s_wdf[256];
    __shared__ float s_red[8][264];
    __shared__ float s_part[8];
    __shared__ float s_bcast;

    s_wdf[tid] = g_Wd[b * 256 + tid];       // bias already folded
    __syncthreads();

    int e0 = lane * 8;
    __half2 wdh[4];
    float wvr[8];
    #pragma unroll
    for (int j = 0; j < 4; j++)
        wdh[j] = __floats2half2_rn(s_wdf[e0 + 2 * j], s_wdf[e0 + 2 * j + 1]);
    #pragma unroll
    for (int j = 0; j < 8; j++) wvr[j] = Wvd[e0 + j];

    const __half* ue = g_Ueh + (size_t)b * T * ENC;
    const __half* xb = g_Xh + (size_t)b * T * ENC;
    float bv = bvd[0];

    float ctx[8] = {};
    float sumexp = 0.f;

    #pragma unroll
    for (int g = 0; g < 4; g++) {
        float acc[4];
        float4 xraw[4];
        {
            float4 uraw[4];
            #pragma unroll
            for (int u = 0; u < 4; u++) {
                int t = warp + (g * 4 + u) * 8;
                int te = t < T ? t : 0;
                uraw[u] = *(const float4*)(ue + te * 256 + e0);
            }
            #pragma unroll
            for (int u = 0; u < 4; u++) {
                int t = warp + (g * 4 + u) * 8;
                int te = t < T ? t : 0;
                xraw[u] = *(const float4*)(xb + te * 256 + e0);
            }
            #pragma unroll
            for (int u = 0; u < 4; u++) {
                const __half2* up = (const __half2*)&uraw[u];
                float a = 0.f;
                #pragma unroll
                for (int j = 0; j < 4; j++) {
                    __half2 th = fast_tanh2(__hadd2(wdh[j], up[j]));
                    float2 f = __half22float2(th);
                    a = fmaf(f.x, wvr[2 * j],     a);
                    a = fmaf(f.y, wvr[2 * j + 1], a);
                }
                acc[u] = a;
            }
        }
        #pragma unroll
        for (int o = 16; o; o >>= 1) {
            #pragma unroll
            for (int u = 0; u < 4; u++)
                acc[u] += __shfl_xor_sync(0xffffffffu, acc[u], o);
        }
        float ew[4];
        #pragma unroll
        for (int u = 0; u < 4; u++) {
            int t = warp + (g * 4 + u) * 8;
            ew[u] = (t < T) ? __expf(acc[u] + bv) : 0.f;
            sumexp += ew[u];
        }
        #pragma unroll
        for (int u = 0; u < 4; u++) {
            const __half2* xp = (const __half2*)&xraw[u];
            #pragma unroll
            for (int j = 0; j < 4; j++) {
                float2 f = __half22float2(xp[j]);
                ctx[2 * j]     = fmaf(ew[u], f.x, ctx[2 * j]);
                ctx[2 * j + 1] = fmaf(ew[u], f.y, ctx[2 * j + 1]);
            }
        }
    }
    #pragma unroll
    for (int j = 0; j < 8; j++) s_red[warp][e0 + j] = ctx[j];
    if (lane == 0) s_part[warp] = sumexp;
    __syncthreads();
    if (tid == 0) {
        float ss = 0.f;
        #pragma unroll
        for (int i = 0; i < 8; i++) ss += s_part[i];
        s_bcast = ss;
    }
    __syncthreads();
    float inv = 1.f / s_bcast;

    float cv = 0.f;
    #pragma unroll
    for (int g = 0; g < 8; g++) cv += s_red[g][tid];
    cv *= inv;
    g_ctx[b * 256 + tid] = cv;

    float yv = cv * Ww[tid];
    #pragma unroll
    for (int o = 16; o; o >>= 1) yv += __shfl_xor_sync(0xffffffffu, yv, o);
    if (lane == 0) s_part[warp] = yv;
    __syncthreads();
    if (tid == 0) {
        float ss = 0.f;
        #pragma unroll
        for (int i = 0; i < 8; i++) ss += s_part[i];
        s_bcast = ss + yhist[b * T + step] * Ww[256] + bw[0];
    }
    __syncthreads();
    float yt = s_bcast;

    // LSTM cell for row b, d = tid — fp32 recurrence, fp16 copies for GEMMs
    const float* gb = g_gates + (size_t)b * 1024;
    float gi = gb[tid]       + yt * Wih[tid];
    float gf = gb[256 + tid] + yt * Wih[256 + tid];
    float gg = gb[512 + tid] + yt * Wih[512 + tid];
    float go = gb[768 + tid] + yt * Wih[768 + tid];
    float ig = 1.f / (1.f + expf(-gi));
    float fg = 1.f / (1.f + expf(-gf));
    float gt = tanhf(gg);
    float og = 1.f / (1.f + expf(-go));
    int nxt = cur ^ 1;
    int idx = b * 256 + tid;
    float cn = fg * g_c[cur][idx] + ig * gt;
    float hn = og * tanhf(cn);
    g_c[nxt][idx] = cn;
    g_h[nxt][idx] = hn;
    g_ch[idx] = __float2half(cn);
    g_hh[idx] = __float2half(hn);
}

// ---------------- final projection -------------------------------------------
__global__ __launch_bounds__(256) void k_final(
    const float* __restrict__ Wfc, const float* __restrict__ bfc,
    float* __restrict__ out, int fin)
{
    int b = blockIdx.x, tid = threadIdx.x, lane = tid & 31, warp = tid >> 5;
    __shared__ float s_part[8];
    float v = g_h[fin][b * 256 + tid] * Wfc[tid]
            + g_ctx[b * 256 + tid] * Wfc[256 + tid];
    #pragma unroll
    for (int o = 16; o; o >>= 1) v += __shfl_xor_sync(0xffffffffu, v, o);
    if (lane == 0) s_part[warp] = v;
    __syncthreads();
    if (tid == 0) {
        float ss = 0.f;
        #pragma unroll
        for (int i = 0; i < 8; i++) ss += s_part[i];
        out[b] = ss + bfc[0];
    }
}

// ---------------- host -------------------------------------------------------
extern "C" void kernel_launch(void* const* d_in, const int* in_sizes, int n_in,
                              void* d_out, int out_size)
{
    const float* X     = (const float*)d_in[0];
    const float* yhist = (const float*)d_in[1];
    const float* W_vd  = (const float*)d_in[2];
    const float* b_vd  = (const float*)d_in[3];
    const float* W_dhs = (const float*)d_in[4];
    const float* b_dhs = (const float*)d_in[5];
    const float* W_Ud  = (const float*)d_in[6];
    const float* b_Ud  = (const float*)d_in[7];
    const float* W_w   = (const float*)d_in[8];
    const float* b_w   = (const float*)d_in[9];
    const float* W_ih  = (const float*)d_in[10];
    const float* W_hh  = (const float*)d_in[11];
    const float* b_ih  = (const float*)d_in[12];
    const float* b_hh  = (const float*)d_in[13];
    const float* W_fc  = (const float*)d_in[14];
    const float* b_fc  = (const float*)d_in[15];
    float* out = (float*)d_out;

    void *p_wh, *p_wdhs, *p_whh;
    cudaGetSymbolAddress(&p_wh, g_Wh);
    cudaGetSymbolAddress(&p_wdhs, g_Wdhs_h);
    cudaGetSymbolAddress(&p_whh, g_Whh_h);

    k_zero_state<<<(BATCH * DEC) / 256, 256>>>();
    k_convert_x<<<((size_t)BATCH * T * ENC) / 4 / 256, 256>>>(X);
    k_convert_w<<<(ENC * ENC) / 256, 256>>>((__half*)p_wh, W_Ud);
    k_convert_w<<<(ENC * 2 * DEC) / 256, 256>>>((__half*)p_wdhs, W_dhs);
    k_convert_w<<<(4 * DEC * DEC) / 256, 256>>>((__half*)p_whh, W_hh);
    {
        dim3 grid(ENC / 64, (BATCH * T) / 64);
        k_ue_wmma<<<grid, 256>>>(b_Ud);
    }

    for (int s = 0; s < T; s++) {
        int cur = s & 1;
        k_wd_gates<<<320, 256>>>(b_dhs, b_ih, b_hh);
        k_attn_cell<<<BATCH, 256>>>(W_vd, b_vd, W_w, b_w, yhist, W_ih, s, cur);
    }

    k_final<<<BATCH, 256>>>(W_fc, b_fc, out, T & 1);
}

// round 13
// speedup vs baseline: 3.8004x; 1.0067x over previous
#include <cuda_runtime.h>
#include <cuda_fp16.h>
#include <mma.h>
#include <math.h>

using namespace nvcuda;

#define BATCH 1024
#define T     127
#define ENC   256
#define DEC   256
#define B_RES 768            // Ue rows for b < B_RES stay L2-resident; rest stream

// ---------------- scratch (device globals) ----------------------------------
__device__ __half g_Ueh[(size_t)BATCH * T * ENC];   // 66.6 MB
__device__ __half g_Xh[(size_t)BATCH * T * ENC];    // 66.6 MB
__device__ __half g_Wh[ENC * ENC];                  // W_Ud fp16
__device__ __half g_Wdhs_h[ENC * 2 * DEC];          // W_dhs fp16 (256x512)
__device__ __half g_Whh_h[4 * DEC * DEC];           // W_hh fp16 (1024x256)
__device__ float  g_h[2][BATCH * DEC];
__device__ float  g_c[2][BATCH * DEC];
__device__ __half g_hh[BATCH * DEC];                // fp16 copy of current h
__device__ __half g_ch[BATCH * DEC];                // fp16 copy of current c
__device__ float  g_Wd[BATCH * ENC];                // bias-folded Wd
__device__ float  g_gates[(size_t)BATCH * 4 * DEC];
__device__ float  g_ctx[BATCH * ENC];

__device__ __forceinline__ __half2 fast_tanh2(__half2 x) {
    return h2tanh_approx(x);
}

// ---------------- init ------------------------------------------------------
__global__ void k_zero_state() {
    int i = blockIdx.x * 256 + threadIdx.x;
    g_h[0][i] = 0.f;
    g_c[0][i] = 0.f;
    g_hh[i] = __float2half(0.f);
    g_ch[i] = __float2half(0.f);
}

// ---------------- converts --------------------------------------------------
__global__ __launch_bounds__(256) void k_convert_x(const float* __restrict__ X) {
    size_t i = ((size_t)blockIdx.x * 256 + threadIdx.x) * 4;
    float4 v = *(const float4*)(X + i);
    *(__half2*)(g_Xh + i)     = __floats2half2_rn(v.x, v.y);
    *(__half2*)(g_Xh + i + 2) = __floats2half2_rn(v.z, v.w);
}
__global__ __launch_bounds__(256) void k_convert_w(__half* dst, const float* __restrict__ src) {
    int i = blockIdx.x * 256 + threadIdx.x;
    dst[i] = __float2half(src[i]);
}

// ---------------- Ue GEMM via fp16 wmma (fp32 accum) --------------------------
__global__ __launch_bounds__(256) void k_ue_wmma(const float* __restrict__ bias)
{
    __shared__ __half sA[64][136];
    __shared__ __half sB[64][136];
    int tid = threadIdx.x;
    int warp = tid >> 5;
    int wm = warp >> 1, wn = warp & 1;
    size_t m0 = (size_t)blockIdx.y * 64;
    int n0 = blockIdx.x * 64;

    wmma::fragment<wmma::accumulator, 16, 16, 16, float> cfrag[2];
    wmma::fill_fragment(cfrag[0], 0.f);
    wmma::fill_fragment(cfrag[1], 0.f);

    for (int kc = 0; kc < 256; kc += 128) {
        #pragma unroll
        for (int i = 0; i < 4; i++) {
            int lin = tid + i * 256;
            int r = lin >> 4, cb = lin & 15;
            *(float4*)&sA[r][cb * 8] =
                *(const float4*)(g_Xh + (m0 + r) * 256 + kc + cb * 8);
        }
        #pragma unroll
        for (int i = 0; i < 4; i++) {
            int lin = tid + i * 256;
            int r = lin >> 4, cb = lin & 15;
            *(float4*)&sB[r][cb * 8] =
                *(const float4*)(g_Wh + (size_t)(n0 + r) * 256 + kc + cb * 8);
        }
        __syncthreads();
        #pragma unroll
        for (int k = 0; k < 128; k += 16) {
            wmma::fragment<wmma::matrix_a, 16, 16, 16, __half, wmma::row_major> afrag;
            wmma::load_matrix_sync(afrag, &sA[wm * 16][k], 136);
            #pragma unroll
            for (int j = 0; j < 2; j++) {
                wmma::fragment<wmma::matrix_b, 16, 16, 16, __half, wmma::col_major> bfrag;
                wmma::load_matrix_sync(bfrag, &sB[wn * 32 + j * 16][k], 136);
                wmma::mma_sync(cfrag[j], afrag, bfrag, cfrag[j]);
            }
        }
        __syncthreads();
    }

    float* cs = (float*)&sA[0][0];
    wmma::store_matrix_sync(cs + (wm * 16) * 68 + wn * 32,      cfrag[0], 68, wmma::mem_row_major);
    wmma::store_matrix_sync(cs + (wm * 16) * 68 + wn * 32 + 16, cfrag[1], 68, wmma::mem_row_major);
    __syncthreads();

    int r = tid >> 2, c0 = (tid & 3) * 16;
    size_t m = m0 + r;
    bool stream = (m >= (size_t)B_RES * T);   // rows for b >= B_RES: evict-first
    __half2* dst = (__half2*)(g_Ueh + m * 256 + n0 + c0);
    #pragma unroll
    for (int j = 0; j < 16; j += 2) {
        float v0 = cs[r * 68 + c0 + j]     + bias[n0 + c0 + j];
        float v1 = cs[r * 68 + c0 + j + 1] + bias[n0 + c0 + j + 1];
        __half2 hv = __floats2half2_rn(v0, v1);
        if (stream) __stcs(dst + (j >> 1), hv);
        else        dst[j >> 1] = hv;
    }
}

// ---------------- Wd + gates via fp16 wmma ------------------------------------
// blocks [0,64): Wd tiles (M=1024,N=256,K=512; A = [h|c] fp16, full K per block)
// blocks [64,320): gates tiles (M=1024,N=1024,K=256; A = h fp16)
__global__ __launch_bounds__(256) void k_wd_gates(
    const float* __restrict__ bdhs,
    const float* __restrict__ bih, const float* __restrict__ bhh)
{
    __shared__ union {
        struct { __half A[64][72]; __half B[64][72]; } h;
        float C[64][68];
    } sm;
    int tid = threadIdx.x;
    int warp = tid >> 5;
    int wm = warp >> 1, wn = warp & 1;
    int bid = blockIdx.x;

    int m0, n0, nk, ldw;
    const __half* Wsrc;
    bool is_wd = (bid < 64);
    if (is_wd) {
        m0 = (bid >> 2) * 64;
        n0 = (bid & 3) * 64;
        nk = 8;  ldw = 512;  Wsrc = g_Wdhs_h;
    } else {
        int rem = bid - 64;
        m0 = (rem >> 4) * 64;
        n0 = (rem & 15) * 64;
        nk = 4;  ldw = 256;  Wsrc = g_Whh_h;
    }

    wmma::fragment<wmma::accumulator, 16, 16, 16, float> cfrag[2];
    wmma::fill_fragment(cfrag[0], 0.f);
    wmma::fill_fragment(cfrag[1], 0.f);

    for (int c = 0; c < nk; c++) {
        int kc = c * 64;
        const __half* Asrc = (kc < 256) ? g_hh : g_ch;
        int kof = (kc < 256) ? kc : (kc - 256);
        #pragma unroll
        for (int i = 0; i < 2; i++) {
            int lin = tid + i * 256;
            int r = lin >> 3, cb = lin & 7;
            *(float4*)&sm.h.A[r][cb * 8] =
                *(const float4*)(Asrc + (size_t)(m0 + r) * 256 + kof + cb * 8);
        }
        #pragma unroll
        for (int i = 0; i < 2; i++) {
            int lin = tid + i * 256;
            int r = lin >> 3, cb = lin & 7;
            *(float4*)&sm.h.B[r][cb * 8] =
                *(const float4*)(Wsrc + (size_t)(n0 + r) * ldw + kc + cb * 8);
        }
        __syncthreads();
        #pragma unroll
        for (int k = 0; k < 64; k += 16) {
            wmma::fragment<wmma::matrix_a, 16, 16, 16, __half, wmma::row_major> afrag;
            wmma::load_matrix_sync(afrag, &sm.h.A[wm * 16][k], 72);
            #pragma unroll
            for (int j = 0; j < 2; j++) {
                wmma::fragment<wmma::matrix_b, 16, 16, 16, __half, wmma::col_major> bfrag;
                wmma::load_matrix_sync(bfrag, &sm.h.B[wn * 32 + j * 16][k], 72);
                wmma::mma_sync(cfrag[j], afrag, bfrag, cfrag[j]);
            }
        }
        __syncthreads();
    }

    wmma::store_matrix_sync(&sm.C[wm * 16][wn * 32],      cfrag[0], 68, wmma::mem_row_major);
    wmma::store_matrix_sync(&sm.C[wm * 16][wn * 32 + 16], cfrag[1], 68, wmma::mem_row_major);
    __syncthreads();

    int r = tid >> 2, c0 = (tid & 3) * 16;
    int m = m0 + r;
    if (is_wd) {
        #pragma unroll
        for (int j = 0; j < 16; j++) {
            int n = n0 + c0 + j;
            g_Wd[m * 256 + n] = sm.C[r][c0 + j] + bdhs[n];
        }
    } else {
        #pragma unroll
        for (int j = 0; j < 16; j++) {
            int n = n0 + c0 + j;
            g_gates[(size_t)m * 1024 + n] = sm.C[r][c0 + j] + bih[n] + bhh[n];
        }
    }
}

// ---------------- fused one-pass attention + LSTM cell -----------------------
__global__ __launch_bounds__(256) void k_attn_cell(
    const float* __restrict__ Wvd, const float* __restrict__ bvd,
    const float* __restrict__ Ww,  const float* __restrict__ bw,
    const float* __restrict__ yhist,
    const float* __restrict__ Wih, int step, int cur)
{
    int b = blockIdx.x;
    int tid = threadIdx.x, lane = tid & 31, warp = tid >> 5;
    __shared__ float s_wdf[256];
    __shared__ float s_red[8][264];
    __shared__ float s_part[8];
    __shared__ float s_bcast;

    s_wdf[tid] = g_Wd[b * 256 + tid];       // bias already folded
    __syncthreads();

    int e0 = lane * 8;
    __half2 wdh[4];
    float wvr[8];
    #pragma unroll
    for (int j = 0; j < 4; j++)
        wdh[j] = __floats2half2_rn(s_wdf[e0 + 2 * j], s_wdf[e0 + 2 * j + 1]);
    #pragma unroll
    for (int j = 0; j < 8; j++) wvr[j] = Wvd[e0 + j];

    const __half* ue = g_Ueh + (size_t)b * T * ENC;
    const __half* xb = g_Xh + (size_t)b * T * ENC;
    float bv = bvd[0];
    bool stream_ue = (b >= B_RES);          // uniform per block

    float ctx[8] = {};
    float sumexp = 0.f;

    #pragma unroll
    for (int g = 0; g < 4; g++) {
        float acc[4];
        float4 xraw[4];
        {
            float4 uraw[4];
            if (stream_ue) {
                #pragma unroll
                for (int u = 0; u < 4; u++) {
                    int t = warp + (g * 4 + u) * 8;
                    int te = t < T ? t : 0;
                    uraw[u] = __ldcs((const float4*)(ue + te * 256 + e0));
                }
            } else {
                #pragma unroll
                for (int u = 0; u < 4; u++) {
                    int t = warp + (g * 4 + u) * 8;
                    int te = t < T ? t : 0;
                    uraw[u] = *(const float4*)(ue + te * 256 + e0);
                }
            }
            #pragma unroll
            for (int u = 0; u < 4; u++) {
                int t = warp + (g * 4 + u) * 8;
                int te = t < T ? t : 0;
                xraw[u] = *(const float4*)(xb + te * 256 + e0);
            }
            #pragma unroll
            for (int u = 0; u < 4; u++) {
                const __half2* up = (const __half2*)&uraw[u];
                float a = 0.f;
                #pragma unroll
                for (int j = 0; j < 4; j++) {
                    __half2 th = fast_tanh2(__hadd2(wdh[j], up[j]));
                    float2 f = __half22float2(th);
                    a = fmaf(f.x, wvr[2 * j],     a);
                    a = fmaf(f.y, wvr[2 * j + 1], a);
                }
                acc[u] = a;
            }
        }
        #pragma unroll
        for (int o = 16; o; o >>= 1) {
            #pragma unroll
            for (int u = 0; u < 4; u++)
                acc[u] += __shfl_xor_sync(0xffffffffu, acc[u], o);
        }
        float ew[4];
        #pragma unroll
        for (int u = 0; u < 4; u++) {
            int t = warp + (g * 4 + u) * 8;
            ew[u] = (t < T) ? __expf(acc[u] + bv) : 0.f;
            sumexp += ew[u];
        }
        #pragma unroll
        for (int u = 0; u < 4; u++) {
            const __half2* xp = (const __half2*)&xraw[u];
            #pragma unroll
            for (int j = 0; j < 4; j++) {
                float2 f = __half22float2(xp[j]);
                ctx[2 * j]     = fmaf(ew[u], f.x, ctx[2 * j]);
                ctx[2 * j + 1] = fmaf(ew[u], f.y, ctx[2 * j + 1]);
            }
        }
    }
    #pragma unroll
    for (int j = 0; j < 8; j++) s_red[warp][e0 + j] = ctx[j];
    if (lane == 0) s_part[warp] = sumexp;
    __syncthreads();
    if (tid == 0) {
        float ss = 0.f;
        #pragma unroll
        for (int i = 0; i < 8; i++) ss += s_part[i];
        s_bcast = ss;
    }
    __syncthreads();
    float inv = 1.f / s_bcast;

    float cv = 0.f;
    #pragma unroll
    for (int g = 0; g < 8; g++) cv += s_red[g][tid];
    cv *= inv;
    g_ctx[b * 256 + tid] = cv;

    float yv = cv * Ww[tid];
    #pragma unroll
    for (int o = 16; o; o >>= 1) yv += __shfl_xor_sync(0xffffffffu, yv, o);
    if (lane == 0) s_part[warp] = yv;
    __syncthreads();
    if (tid == 0) {
        float ss = 0.f;
        #pragma unroll
        for (int i = 0; i < 8; i++) ss += s_part[i];
        s_bcast = ss + yhist[b * T + step] * Ww[256] + bw[0];
    }
    __syncthreads();
    float yt = s_bcast;

    // LSTM cell for row b, d = tid — fp32 recurrence, fp16 copies for GEMMs
    const float* gb = g_gates + (size_t)b * 1024;
    float gi = gb[tid]       + yt * Wih[tid];
    float gf = gb[256 + tid] + yt * Wih[256 + tid];
    float gg = gb[512 + tid] + yt * Wih[512 + tid];
    float go = gb[768 + tid] + yt * Wih[768 + tid];
    float ig = 1.f / (1.f + expf(-gi));
    float fg = 1.f / (1.f + expf(-gf));
    float gt = tanhf(gg);
    float og = 1.f / (1.f + expf(-go));
    int nxt = cur ^ 1;
    int idx = b * 256 + tid;
    float cn = fg * g_c[cur][idx] + ig * gt;
    float hn = og * tanhf(cn);
    g_c[nxt][idx] = cn;
    g_h[nxt][idx] = hn;
    g_ch[idx] = __float2half(cn);
    g_hh[idx] = __float2half(hn);
}

// ---------------- final projection -------------------------------------------
__global__ __launch_bounds__(256) void k_final(
    const float* __restrict__ Wfc, const float* __restrict__ bfc,
    float* __restrict__ out, int fin)
{
    int b = blockIdx.x, tid = threadIdx.x, lane = tid & 31, warp = tid >> 5;
    __shared__ float s_part[8];
    float v = g_h[fin][b * 256 + tid] * Wfc[tid]
            + g_ctx[b * 256 + tid] * Wfc[256 + tid];
    #pragma unroll
    for (int o = 16; o; o >>= 1) v += __shfl_xor_sync(0xffffffffu, v, o);
    if (lane == 0) s_part[warp] = v;
    __syncthreads();
    if (tid == 0) {
        float ss = 0.f;
        #pragma unroll
        for (int i = 0; i < 8; i++) ss += s_part[i];
        out[b] = ss + bfc[0];
    }
}

// ---------------- host -------------------------------------------------------
extern "C" void kernel_launch(void* const* d_in, const int* in_sizes, int n_in,
                              void* d_out, int out_size)
{
    const float* X     = (const float*)d_in[0];
    const float* yhist = (const float*)d_in[1];
    const float* W_vd  = (const float*)d_in[2];
    const float* b_vd  = (const float*)d_in[3];
    const float* W_dhs = (const float*)d_in[4];
    const float* b_dhs = (const float*)d_in[5];
    const float* W_Ud  = (const float*)d_in[6];
    const float* b_Ud  = (const float*)d_in[7];
    const float* W_w   = (const float*)d_in[8];
    const float* b_w   = (const float*)d_in[9];
    const float* W_ih  = (const float*)d_in[10];
    const float* W_hh  = (const float*)d_in[11];
    const float* b_ih  = (const float*)d_in[12];
    const float* b_hh  = (const float*)d_in[13];
    const float* W_fc  = (const float*)d_in[14];
    const float* b_fc  = (const float*)d_in[15];
    float* out = (float*)d_out;

    void *p_wh, *p_wdhs, *p_whh;
    cudaGetSymbolAddress(&p_wh, g_Wh);
    cudaGetSymbolAddress(&p_wdhs, g_Wdhs_h);
    cudaGetSymbolAddress(&p_whh, g_Whh_h);

    k_zero_state<<<(BATCH * DEC) / 256, 256>>>();
    k_convert_x<<<((size_t)BATCH * T * ENC) / 4 / 256, 256>>>(X);
    k_convert_w<<<(ENC * ENC) / 256, 256>>>((__half*)p_wh, W_Ud);
    k_convert_w<<<(ENC * 2 * DEC) / 256, 256>>>((__half*)p_wdhs, W_dhs);
    k_convert_w<<<(4 * DEC * DEC) / 256, 256>>>((__half*)p_whh, W_hh);
    {
        dim3 grid(ENC / 64, (BATCH * T) / 64);
        k_ue_wmma<<<grid, 256>>>(b_Ud);
    }

    for (int s = 0; s < T; s++) {
        int cur = s & 1;
        k_wd_gates<<<320, 256>>>(b_dhs, b_ih, b_hh);
        k_attn_cell<<<BATCH, 256>>>(W_vd, b_vd, W_w, b_w, yhist, W_ih, s, cur);
    }

    k_final<<<BATCH, 256>>>(W_fc, b_fc, out, T & 1);
}

// round 14
// speedup vs baseline: 4.7054x; 1.2381x over previous
#include <cuda_runtime.h>
#include <cuda_fp16.h>
#include <mma.h>
#include <math.h>

using namespace nvcuda;

#define BATCH 1024
#define T     127
#define ENC   256
#define DEC   256

// ---------------- scratch (device globals) ----------------------------------
__device__ __half g_Ueh[(size_t)BATCH * T * ENC];   // 66.6 MB (streamed, never cached)
__device__ __half g_Xh[(size_t)BATCH * T * ENC];    // 66.6 MB (L2-resident target)
__device__ __half g_Wh[ENC * ENC];                  // W_Ud fp16
__device__ __half g_Wdhs_h[ENC * 2 * DEC];          // W_dhs fp16 (256x512)
__device__ __half g_Whh_h[4 * DEC * DEC];           // W_hh fp16 (1024x256)
__device__ float  g_h[2][BATCH * DEC];
__device__ float  g_c[2][BATCH * DEC];
__device__ __half g_hh[BATCH * DEC];                // fp16 copy of current h
__device__ __half g_ch[BATCH * DEC];                // fp16 copy of current c
__device__ float  g_Wd[BATCH * ENC];                // bias-folded Wd
__device__ float  g_gates[(size_t)BATCH * 4 * DEC];
__device__ float  g_ctx[BATCH * ENC];

__device__ __forceinline__ __half2 fast_tanh2(__half2 x) {
    return h2tanh_approx(x);
}

// ---------------- init ------------------------------------------------------
__global__ void k_zero_state() {
    int i = blockIdx.x * 256 + threadIdx.x;
    g_h[0][i] = 0.f;
    g_c[0][i] = 0.f;
    g_hh[i] = __float2half(0.f);
    g_ch[i] = __float2half(0.f);
}

// ---------------- converts --------------------------------------------------
__global__ __launch_bounds__(256) void k_convert_x(const float* __restrict__ X) {
    size_t i = ((size_t)blockIdx.x * 256 + threadIdx.x) * 4;
    float4 v = *(const float4*)(X + i);
    *(__half2*)(g_Xh + i)     = __floats2half2_rn(v.x, v.y);
    *(__half2*)(g_Xh + i + 2) = __floats2half2_rn(v.z, v.w);
}
__global__ __launch_bounds__(256) void k_convert_w(__half* dst, const float* __restrict__ src) {
    int i = blockIdx.x * 256 + threadIdx.x;
    dst[i] = __float2half(src[i]);
}

// ---------------- Ue GEMM via fp16 wmma (fp32 accum) --------------------------
__global__ __launch_bounds__(256) void k_ue_wmma(const float* __restrict__ bias)
{
    __shared__ __half sA[64][136];
    __shared__ __half sB[64][136];
    int tid = threadIdx.x;
    int warp = tid >> 5;
    int wm = warp >> 1, wn = warp & 1;
    size_t m0 = (size_t)blockIdx.y * 64;
    int n0 = blockIdx.x * 64;

    wmma::fragment<wmma::accumulator, 16, 16, 16, float> cfrag[2];
    wmma::fill_fragment(cfrag[0], 0.f);
    wmma::fill_fragment(cfrag[1], 0.f);

    for (int kc = 0; kc < 256; kc += 128) {
        #pragma unroll
        for (int i = 0; i < 4; i++) {
            int lin = tid + i * 256;
            int r = lin >> 4, cb = lin & 15;
            *(float4*)&sA[r][cb * 8] =
                *(const float4*)(g_Xh + (m0 + r) * 256 + kc + cb * 8);
        }
        #pragma unroll
        for (int i = 0; i < 4; i++) {
            int lin = tid + i * 256;
            int r = lin >> 4, cb = lin & 15;
            *(float4*)&sB[r][cb * 8] =
                *(const float4*)(g_Wh + (size_t)(n0 + r) * 256 + kc + cb * 8);
        }
        __syncthreads();
        #pragma unroll
        for (int k = 0; k < 128; k += 16) {
            wmma::fragment<wmma::matrix_a, 16, 16, 16, __half, wmma::row_major> afrag;
            wmma::load_matrix_sync(afrag, &sA[wm * 16][k], 136);
            #pragma unroll
            for (int j = 0; j < 2; j++) {
                wmma::fragment<wmma::matrix_b, 16, 16, 16, __half, wmma::col_major> bfrag;
                wmma::load_matrix_sync(bfrag, &sB[wn * 32 + j * 16][k], 136);
                wmma::mma_sync(cfrag[j], afrag, bfrag, cfrag[j]);
            }
        }
        __syncthreads();
    }

    float* cs = (float*)&sA[0][0];
    wmma::store_matrix_sync(cs + (wm * 16) * 68 + wn * 32,      cfrag[0], 68, wmma::mem_row_major);
    wmma::store_matrix_sync(cs + (wm * 16) * 68 + wn * 32 + 16, cfrag[1], 68, wmma::mem_row_major);
    __syncthreads();

    int r = tid >> 2, c0 = (tid & 3) * 16;
    size_t m = m0 + r;
    __half2* dst = (__half2*)(g_Ueh + m * 256 + n0 + c0);
    #pragma unroll
    for (int j = 0; j < 16; j += 2) {
        float v0 = cs[r * 68 + c0 + j]     + bias[n0 + c0 + j];
        float v1 = cs[r * 68 + c0 + j + 1] + bias[n0 + c0 + j + 1];
        __stcs(dst + (j >> 1), __floats2half2_rn(v0, v1));   // Ue: evict-first
    }
}

// ---------------- Wd + gates via fp16 wmma ------------------------------------
// blocks [0,64): Wd tiles (M=1024,N=256,K=512; A = [h|c] fp16, full K per block)
// blocks [64,320): gates tiles (M=1024,N=1024,K=256; A = h fp16)
__global__ __launch_bounds__(256) void k_wd_gates(
    const float* __restrict__ bdhs,
    const float* __restrict__ bih, const float* __restrict__ bhh)
{
    __shared__ union {
        struct { __half A[64][72]; __half B[64][72]; } h;
        float C[64][68];
    } sm;
    int tid = threadIdx.x;
    int warp = tid >> 5;
    int wm = warp >> 1, wn = warp & 1;
    int bid = blockIdx.x;

    int m0, n0, nk, ldw;
    const __half* Wsrc;
    bool is_wd = (bid < 64);
    if (is_wd) {
        m0 = (bid >> 2) * 64;
        n0 = (bid & 3) * 64;
        nk = 8;  ldw = 512;  Wsrc = g_Wdhs_h;
    } else {
        int rem = bid - 64;
        m0 = (rem >> 4) * 64;
        n0 = (rem & 15) * 64;
        nk = 4;  ldw = 256;  Wsrc = g_Whh_h;
    }

    wmma::fragment<wmma::accumulator, 16, 16, 16, float> cfrag[2];
    wmma::fill_fragment(cfrag[0], 0.f);
    wmma::fill_fragment(cfrag[1], 0.f);

    for (int c = 0; c < nk; c++) {
        int kc = c * 64;
        const __half* Asrc = (kc < 256) ? g_hh : g_ch;
        int kof = (kc < 256) ? kc : (kc - 256);
        #pragma unroll
        for (int i = 0; i < 2; i++) {
            int lin = tid + i * 256;
            int r = lin >> 3, cb = lin & 7;
            *(float4*)&sm.h.A[r][cb * 8] =
                *(const float4*)(Asrc + (size_t)(m0 + r) * 256 + kof + cb * 8);
        }
        #pragma unroll
        for (int i = 0; i < 2; i++) {
            int lin = tid + i * 256;
            int r = lin >> 3, cb = lin & 7;
            *(float4*)&sm.h.B[r][cb * 8] =
                *(const float4*)(Wsrc + (size_t)(n0 + r) * ldw + kc + cb * 8);
        }
        __syncthreads();
        #pragma unroll
        for (int k = 0; k < 64; k += 16) {
            wmma::fragment<wmma::matrix_a, 16, 16, 16, __half, wmma::row_major> afrag;
            wmma::load_matrix_sync(afrag, &sm.h.A[wm * 16][k], 72);
            #pragma unroll
            for (int j = 0; j < 2; j++) {
                wmma::fragment<wmma::matrix_b, 16, 16, 16, __half, wmma::col_major> bfrag;
                wmma::load_matrix_sync(bfrag, &sm.h.B[wn * 32 + j * 16][k], 72);
                wmma::mma_sync(cfrag[j], afrag, bfrag, cfrag[j]);
            }
        }
        __syncthreads();
    }

    wmma::store_matrix_sync(&sm.C[wm * 16][wn * 32],      cfrag[0], 68, wmma::mem_row_major);
    wmma::store_matrix_sync(&sm.C[wm * 16][wn * 32 + 16], cfrag[1], 68, wmma::mem_row_major);
    __syncthreads();

    int r = tid >> 2, c0 = (tid & 3) * 16;
    int m = m0 + r;
    if (is_wd) {
        #pragma unroll
        for (int j = 0; j < 16; j++) {
            int n = n0 + c0 + j;
            g_Wd[m * 256 + n] = sm.C[r][c0 + j] + bdhs[n];
        }
    } else {
        #pragma unroll
        for (int j = 0; j < 16; j++) {
            int n = n0 + c0 + j;
            g_gates[(size_t)m * 1024 + n] = sm.C[r][c0 + j] + bih[n] + bhh[n];
        }
    }
}

// ---------------- fused one-pass attention + LSTM cell -----------------------
__global__ __launch_bounds__(256) void k_attn_cell(
    const float* __restrict__ Wvd, const float* __restrict__ bvd,
    const float* __restrict__ Ww,  const float* __restrict__ bw,
    const float* __restrict__ yhist,
    const float* __restrict__ Wih, int step, int cur)
{
    int b = blockIdx.x;
    int tid = threadIdx.x, lane = tid & 31, warp = tid >> 5;
    __shared__ float s_wdf[256];
    __shared__ float s_red[8][264];
    __shared__ float s_part[8];
    __shared__ float s_bcast;

    s_wdf[tid] = g_Wd[b * 256 + tid];       // bias already folded
    __syncthreads();

    int e0 = lane * 8;
    __half2 wdh[4];
    float wvr[8];
    #pragma unroll
    for (int j = 0; j < 4; j++)
        wdh[j] = __floats2half2_rn(s_wdf[e0 + 2 * j], s_wdf[e0 + 2 * j + 1]);
    #pragma unroll
    for (int j = 0; j < 8; j++) wvr[j] = Wvd[e0 + j];

    const __half* ue = g_Ueh + (size_t)b * T * ENC;
    const __half* xb = g_Xh + (size_t)b * T * ENC;
    float bv = bvd[0];

    float ctx[8] = {};
    float sumexp = 0.f;

    #pragma unroll
    for (int g = 0; g < 4; g++) {
        float acc[4];
        float4 xraw[4];
        {
            float4 uraw[4];
            #pragma unroll
            for (int u = 0; u < 4; u++) {
                int t = warp + (g * 4 + u) * 8;
                int te = t < T ? t : 0;
                uraw[u] = __ldcs((const float4*)(ue + te * 256 + e0));  // stream Ue
            }
            #pragma unroll
            for (int u = 0; u < 4; u++) {
                int t = warp + (g * 4 + u) * 8;
                int te = t < T ? t : 0;
                xraw[u] = *(const float4*)(xb + te * 256 + e0);         // X: L2-resident
            }
            #pragma unroll
            for (int u = 0; u < 4; u++) {
                const __half2* up = (const __half2*)&uraw[u];
                float a = 0.f;
                #pragma unroll
                for (int j = 0; j < 4; j++) {
                    __half2 th = fast_tanh2(__hadd2(wdh[j], up[j]));
                    float2 f = __half22float2(th);
                    a = fmaf(f.x, wvr[2 * j],     a);
                    a = fmaf(f.y, wvr[2 * j + 1], a);
                }
                acc[u] = a;
            }
        }
        #pragma unroll
        for (int o = 16; o; o >>= 1) {
            #pragma unroll
            for (int u = 0; u < 4; u++)
                acc[u] += __shfl_xor_sync(0xffffffffu, acc[u], o);
        }
        float ew[4];
        #pragma unroll
        for (int u = 0; u < 4; u++) {
            int t = warp + (g * 4 + u) * 8;
            ew[u] = (t < T) ? __expf(acc[u] + bv) : 0.f;
            sumexp += ew[u];
        }
        #pragma unroll
        for (int u = 0; u < 4; u++) {
            const __half2* xp = (const __half2*)&xraw[u];
            #pragma unroll
            for (int j = 0; j < 4; j++) {
                float2 f = __half22float2(xp[j]);
                ctx[2 * j]     = fmaf(ew[u], f.x, ctx[2 * j]);
                ctx[2 * j + 1] = fmaf(ew[u], f.y, ctx[2 * j + 1]);
            }
        }
    }
    #pragma unroll
    for (int j = 0; j < 8; j++) s_red[warp][e0 + j] = ctx[j];
    if (lane == 0) s_part[warp] = sumexp;
    __syncthreads();
    if (tid == 0) {
        float ss = 0.f;
        #pragma unroll
        for (int i = 0; i < 8; i++) ss += s_part[i];
        s_bcast = ss;
    }
    __syncthreads();
    float inv = 1.f / s_bcast;

    float cv = 0.f;
    #pragma unroll
    for (int g = 0; g < 8; g++) cv += s_red[g][tid];
    cv *= inv;
    g_ctx[b * 256 + tid] = cv;

    float yv = cv * Ww[tid];
    #pragma unroll
    for (int o = 16; o; o >>= 1) yv += __shfl_xor_sync(0xffffffffu, yv, o);
    if (lane == 0) s_part[warp] = yv;
    __syncthreads();
    if (tid == 0) {
        float ss = 0.f;
        #pragma unroll
        for (int i = 0; i < 8; i++) ss += s_part[i];
        s_bcast = ss + yhist[b * T + step] * Ww[256] + bw[0];
    }
    __syncthreads();
    float yt = s_bcast;

    // LSTM cell for row b, d = tid — fp32 recurrence, fp16 copies for GEMMs
    const float* gb = g_gates + (size_t)b * 1024;
    float gi = gb[tid]       + yt * Wih[tid];
    float gf = gb[256 + tid] + yt * Wih[256 + tid];
    float gg = gb[512 + tid] + yt * Wih[512 + tid];
    float go = gb[768 + tid] + yt * Wih[768 + tid];
    float ig = 1.f / (1.f + expf(-gi));
    float fg = 1.f / (1.f + expf(-gf));
    float gt = tanhf(gg);
    float og = 1.f / (1.f + expf(-go));
    int nxt = cur ^ 1;
    int idx = b * 256 + tid;
    float cn = fg * g_c[cur][idx] + ig * gt;
    float hn = og * tanhf(cn);
    g_c[nxt][idx] = cn;
    g_h[nxt][idx] = hn;
    g_ch[idx] = __float2half(cn);
    g_hh[idx] = __float2half(hn);
}

// ---------------- final projection -------------------------------------------
__global__ __launch_bounds__(256) void k_final(
    const float* __restrict__ Wfc, const float* __restrict__ bfc,
    float* __restrict__ out, int fin)
{
    int b = blockIdx.x, tid = threadIdx.x, lane = tid & 31, warp = tid >> 5;
    __shared__ float s_part[8];
    float v = g_h[fin][b * 256 + tid] * Wfc[tid]
            + g_ctx[b * 256 + tid] * Wfc[256 + tid];
    #pragma unroll
    for (int o = 16; o; o >>= 1) v += __shfl_xor_sync(0xffffffffu, v, o);
    if (lane == 0) s_part[warp] = v;
    __syncthreads();
    if (tid == 0) {
        float ss = 0.f;
        #pragma unroll
        for (int i = 0; i < 8; i++) ss += s_part[i];
        out[b] = ss + bfc[0];
    }
}

// ---------------- host -------------------------------------------------------
extern "C" void kernel_launch(void* const* d_in, const int* in_sizes, int n_in,
                              void* d_out, int out_size)
{
    const float* X     = (const float*)d_in[0];
    const float* yhist = (const float*)d_in[1];
    const float* W_vd  = (const float*)d_in[2];
    const float* b_vd  = (const float*)d_in[3];
    const float* W_dhs = (const float*)d_in[4];
    const float* b_dhs = (const float*)d_in[5];
    const float* W_Ud  = (const float*)d_in[6];
    const float* b_Ud  = (const float*)d_in[7];
    const float* W_w   = (const float*)d_in[8];
    const float* b_w   = (const float*)d_in[9];
    const float* W_ih  = (const float*)d_in[10];
    const float* W_hh  = (const float*)d_in[11];
    const float* b_ih  = (const float*)d_in[12];
    const float* b_hh  = (const float*)d_in[13];
    const float* W_fc  = (const float*)d_in[14];
    const float* b_fc  = (const float*)d_in[15];
    float* out = (float*)d_out;

    void *p_wh, *p_wdhs, *p_whh;
    cudaGetSymbolAddress(&p_wh, g_Wh);
    cudaGetSymbolAddress(&p_wdhs, g_Wdhs_h);
    cudaGetSymbolAddress(&p_whh, g_Whh_h);

    k_zero_state<<<(BATCH * DEC) / 256, 256>>>();
    k_convert_x<<<((size_t)BATCH * T * ENC) / 4 / 256, 256>>>(X);
    k_convert_w<<<(ENC * ENC) / 256, 256>>>((__half*)p_wh, W_Ud);
    k_convert_w<<<(ENC * 2 * DEC) / 256, 256>>>((__half*)p_wdhs, W_dhs);
    k_convert_w<<<(4 * DEC * DEC) / 256, 256>>>((__half*)p_whh, W_hh);
    {
        dim3 grid(ENC / 64, (BATCH * T) / 64);
        k_ue_wmma<<<grid, 256>>>(b_Ud);
    }

    for (int s = 0; s < T; s++) {
        int cur = s & 1;
        k_wd_gates<<<320, 256>>>(b_dhs, b_ih, b_hh);
        k_attn_cell<<<BATCH, 256>>>(W_vd, b_vd, W_w, b_w, yhist, W_ih, s, cur);
    }

    k_final<<<BATCH, 256>>>(W_fc, b_fc, out, T & 1);
}